// round 13
// baseline (speedup 1.0000x reference)
#include <cuda_runtime.h>
#include <cuda_bf16.h>
#include <math.h>
#include <stdint.h>

// ---------------- problem constants ----------------
#define Bq   4
#define Sq   1024
#define Dq   1024
#define Hq   16
#define Lq   8
#define Vq   50257
#define HDq  64
#define D3q  (3*Dq)
#define D4q  (4*Dq)
#define BSq  (Bq*Sq)
#define SCALEq 0.125f

// ---------------- scratch (device globals) ----------------
__device__ float g_x [(size_t)BSq*Dq];
__device__ float g_xf[Bq*Dq];
__device__ float g_pt[(size_t)2*BSq*D4q];         // split-K fp32 partials (134MB)
__device__ __nv_bfloat16 g_ah[(size_t)BSq*Dq];
__device__ __nv_bfloat16 g_al[(size_t)BSq*Dq];
__device__ __nv_bfloat16 g_qh[(size_t)BSq*D3q];
__device__ __nv_bfloat16 g_ql[(size_t)BSq*D3q];
__device__ __nv_bfloat16 g_oh[(size_t)BSq*Dq];
__device__ __nv_bfloat16 g_ol[(size_t)BSq*Dq];
__device__ __nv_bfloat16 g_mh[(size_t)BSq*D4q];
__device__ __nv_bfloat16 g_ml[(size_t)BSq*D4q];
__device__ __nv_bfloat16 g_bh[(size_t)D4q*Dq];
__device__ __nv_bfloat16 g_bl[(size_t)D4q*Dq];

// ---------------- PTX helpers (sm_80-level, valid on compute_103) ----------
__device__ __forceinline__ uint32_t smem_u32(const void* p) {
    uint32_t a;
    asm("{ .reg .u64 t; cvta.to.shared.u64 t, %1; cvt.u32.u64 %0, t; }" : "=r"(a) : "l"(p));
    return a;
}
#define CP_ASYNC16(dst, src) \
    asm volatile("cp.async.cg.shared.global [%0], [%1], 16;" :: "r"(dst), "l"(src))
#define CP_COMMIT()  asm volatile("cp.async.commit_group;" ::: "memory")
#define CP_WAIT1()   asm volatile("cp.async.wait_group 1;" ::: "memory")
#define CP_WAIT0()   asm volatile("cp.async.wait_group 0;" ::: "memory")

__device__ __forceinline__ void ldmx4(uint32_t addr, uint32_t& r0, uint32_t& r1,
                                      uint32_t& r2, uint32_t& r3) {
    asm volatile("ldmatrix.sync.aligned.m8n8.x4.shared.b16 {%0,%1,%2,%3}, [%4];"
        : "=r"(r0), "=r"(r1), "=r"(r2), "=r"(r3) : "r"(addr));
}
__device__ __forceinline__ void ldmx4t(uint32_t addr, uint32_t& r0, uint32_t& r1,
                                       uint32_t& r2, uint32_t& r3) {
    asm volatile("ldmatrix.sync.aligned.m8n8.x4.trans.shared.b16 {%0,%1,%2,%3}, [%4];"
        : "=r"(r0), "=r"(r1), "=r"(r2), "=r"(r3) : "r"(addr));
}
__device__ __forceinline__ void mma16816(float* c, const uint32_t* a,
                                         uint32_t b0, uint32_t b1) {
    asm volatile("mma.sync.aligned.m16n8k16.row.col.f32.bf16.bf16.f32 "
        "{%0,%1,%2,%3}, {%4,%5,%6,%7}, {%8,%9}, {%0,%1,%2,%3};"
        : "+f"(c[0]), "+f"(c[1]), "+f"(c[2]), "+f"(c[3])
        : "r"(a[0]), "r"(a[1]), "r"(a[2]), "r"(a[3]), "r"(b0), "r"(b1));
}
__device__ __forceinline__ uint32_t pk2(float lo, float hi) {
    uint32_t r;
    asm("cvt.rn.bf16x2.f32 %0, %1, %2;" : "=r"(r) : "f"(hi), "f"(lo));
    return r;
}

// ---------------- transpose + split (vectorized): W [K,N] -> [N,K] hi/lo ----
__global__ __launch_bounds__(256) void splitT_kernel(const float* __restrict__ W,
                                                     __nv_bfloat16* __restrict__ BhT,
                                                     __nv_bfloat16* __restrict__ BlT,
                                                     int K, int N) {
    __shared__ float t[32][33];
    int n0 = blockIdx.x * 32, k0 = blockIdx.y * 32;
    int tid = threadIdx.x;
    {
        int r  = tid >> 3;
        int c4 = tid & 7;
        float4 v = *(const float4*)(W + (size_t)(k0 + r) * N + n0 + c4 * 4);
        t[r][c4 * 4 + 0] = v.x;
        t[r][c4 * 4 + 1] = v.y;
        t[r][c4 * 4 + 2] = v.z;
        t[r][c4 * 4 + 3] = v.w;
    }
    __syncthreads();
    {
        int n = tid >> 3;
        #pragma unroll
        for (int i = 0; i < 2; i++) {
            int kp = (tid & 7) + i * 8;
            int k  = kp * 2;
            float v0 = t[k][n];
            float v1 = t[k + 1][n];
            __nv_bfloat16 h0 = __float2bfloat16(v0);
            __nv_bfloat16 h1 = __float2bfloat16(v1);
            float l0 = v0 - __bfloat162float(h0);
            float l1 = v1 - __bfloat162float(h1);
            size_t off = (size_t)(n0 + n) * K + k0 + k;
            *(__nv_bfloat162*)(BhT + off) = __nv_bfloat162(h0, h1);
            *(__nv_bfloat162*)(BlT + off) =
                __nv_bfloat162(__float2bfloat16(l0), __float2bfloat16(l1));
        }
    }
}

// ---------------- HMMA GEMM (R8/R11-exact body) ------------------------------
#define TILE_B  8192
#define STAGE_B (4*TILE_B)
#define HM_SMEM (3*STAGE_B)

template<int EPI, int OSPLIT>
__global__ __launch_bounds__(256, 2) void hmma_gemm(const __nv_bfloat16* __restrict__ Ah,
                                                    const __nv_bfloat16* __restrict__ Al,
                                                    const __nv_bfloat16* __restrict__ Bh,
                                                    const __nv_bfloat16* __restrict__ Bl,
                                                    const float* __restrict__ bias,
                                                    const float* __restrict__ res,
                                                    float* __restrict__ C,
                                                    __nv_bfloat16* __restrict__ Ch,
                                                    __nv_bfloat16* __restrict__ Cl,
                                                    int M, int N, int K) {
    extern __shared__ char smem[];
    const uint32_t sbase = smem_u32(smem);
    const int tid = threadIdx.x;
    const int lane = tid & 31;
    const int warp = tid >> 5;
    const int warpM = warp & 3;
    const int warpN = warp >> 2;
    const int bx = blockIdx.x, by = blockIdx.y;

    const __nv_bfloat16* gA[2] = { Ah + (size_t)(by * 128) * K,
                                   Al + (size_t)(by * 128) * K };
    const __nv_bfloat16* gB[2] = { Bh + (size_t)(bx * 128) * K,
                                   Bl + (size_t)(bx * 128) * K };

    float acc[2][8][4];
    #pragma unroll
    for (int i = 0; i < 2; i++)
        #pragma unroll
        for (int j = 0; j < 8; j++)
            #pragma unroll
            for (int q = 0; q < 4; q++) acc[i][j][q] = 0.f;

    auto issue = [&](int s, int k0) {
        uint32_t stb = sbase + s * STAGE_B;
        #pragma unroll
        for (int t = 0; t < 8; t++) {
            const int tile = t >> 1;
            int w = ((t & 1) << 8) + tid;
            int r = w >> 2, seg = w & 3;
            int sw = seg ^ ((r >> 1) & 3);
            uint32_t dst = stb + tile * TILE_B + r * 64 + sw * 16;
            const __nv_bfloat16* src =
                (tile == 0 ? gA[0] : tile == 1 ? gA[1] : tile == 2 ? gB[0] : gB[1])
                + (size_t)r * K + k0 + seg * 8;
            CP_ASYNC16(dst, src);
        }
    };

    const int frow = lane & 15;
    const int fku  = lane >> 4;

    auto compute = [&](int s) {
        uint32_t stb = sbase + s * STAGE_B;
        #pragma unroll
        for (int ks = 0; ks < 2; ks++) {
            uint32_t ah[2][4], al[2][4];
            #pragma unroll
            for (int mi = 0; mi < 2; mi++) {
                int R = warpM * 32 + mi * 16 + frow;
                int u = (ks * 2 + fku) ^ ((R >> 1) & 3);
                uint32_t ad = stb + (uint32_t)(R * 64 + u * 16);
                ldmx4(ad, ah[mi][0], ah[mi][1], ah[mi][2], ah[mi][3]);
                ldmx4(ad + TILE_B, al[mi][0], al[mi][1], al[mi][2], al[mi][3]);
            }
            #pragma unroll
            for (int np = 0; np < 4; np++) {
                uint32_t bh4[4], bl4[4];
                int R = warpN * 64 + np * 16 + frow;
                int u = (ks * 2 + fku) ^ ((R >> 1) & 3);
                uint32_t bd = stb + 2 * TILE_B + (uint32_t)(R * 64 + u * 16);
                ldmx4(bd, bh4[0], bh4[1], bh4[2], bh4[3]);
                ldmx4(bd + TILE_B, bl4[0], bl4[1], bl4[2], bl4[3]);
                mma16816(acc[0][2*np],   ah[0], bh4[0], bh4[2]);
                mma16816(acc[1][2*np],   ah[1], bh4[0], bh4[2]);
                mma16816(acc[0][2*np+1], ah[0], bh4[1], bh4[3]);
                mma16816(acc[1][2*np+1], ah[1], bh4[1], bh4[3]);
                mma16816(acc[0][2*np],   ah[0], bl4[0], bl4[2]);
                mma16816(acc[1][2*np],   ah[1], bl4[0], bl4[2]);
                mma16816(acc[0][2*np+1], ah[0], bl4[1], bl4[3]);
                mma16816(acc[1][2*np+1], ah[1], bl4[1], bl4[3]);
                mma16816(acc[0][2*np],   al[0], bh4[0], bh4[2]);
                mma16816(acc[1][2*np],   al[1], bh4[0], bh4[2]);
                mma16816(acc[0][2*np+1], al[0], bh4[1], bh4[3]);
                mma16816(acc[1][2*np+1], al[1], bh4[1], bh4[3]);
            }
        }
    };

    const int nch = K >> 5;
    issue(0, 0);
    CP_COMMIT();
    issue(1, 32);
    CP_COMMIT();
    int sc = 0, si = 2;
    for (int c = 0; c < nch; c++) {
        CP_WAIT1();
        __syncthreads();
        if (c + 2 < nch) {
            issue(si, (c + 2) << 5);
            CP_COMMIT();
            if (++si == 3) si = 0;
        }
        compute(sc);
        if (++sc == 3) sc = 0;
    }

    const int tr = lane >> 2;
    const int tc = (lane & 3) * 2;
    const int grow0 = by * 128 + warpM * 32;
    const int gcol0 = bx * 128 + warpN * 64;
    #pragma unroll
    for (int mi = 0; mi < 2; mi++) {
        #pragma unroll
        for (int ni = 0; ni < 8; ni++) {
            int col = gcol0 + ni * 8 + tc;
            float b0 = bias[col], b1 = bias[col + 1];
            #pragma unroll
            for (int half = 0; half < 2; half++) {
                int row = grow0 + mi * 16 + tr + half * 8;
                float v0 = acc[mi][ni][half * 2 + 0] + b0;
                float v1 = acc[mi][ni][half * 2 + 1] + b1;
                if (EPI == 1) {
                    const float* rp = res + (size_t)row * N + col;
                    v0 += rp[0];
                    v1 += rp[1];
                }
                if (EPI == 2) {
                    v0 = 0.5f * v0 * (1.0f + erff(v0 * 0.70710678118654752f));
                    v1 = 0.5f * v1 * (1.0f + erff(v1 * 0.70710678118654752f));
                }
                if (OSPLIT) {
                    __nv_bfloat16 h0 = __float2bfloat16(v0);
                    __nv_bfloat16 h1 = __float2bfloat16(v1);
                    float l0 = v0 - __bfloat162float(h0);
                    float l1 = v1 - __bfloat162float(h1);
                    size_t off = (size_t)row * N + col;
                    *(__nv_bfloat162*)(Ch + off) = __nv_bfloat162(h0, h1);
                    *(__nv_bfloat162*)(Cl + off) =
                        __nv_bfloat162(__float2bfloat16(l0), __float2bfloat16(l1));
                } else {
                    *(float2*)(C + (size_t)row * N + col) = make_float2(v0, v1);
                }
            }
        }
    }
}

// ---------------- split-K partial GEMM: Cp[z] = A @ B^T over K/2 chunk -------
__global__ __launch_bounds__(256, 2) void hmma_part(const __nv_bfloat16* __restrict__ Ah,
                                                    const __nv_bfloat16* __restrict__ Al,
                                                    const __nv_bfloat16* __restrict__ Bh,
                                                    const __nv_bfloat16* __restrict__ Bl,
                                                    float* __restrict__ Cp,
                                                    int M, int N, int K) {
    extern __shared__ char smem[];
    const uint32_t sbase = smem_u32(smem);
    const int tid = threadIdx.x;
    const int lane = tid & 31;
    const int warp = tid >> 5;
    const int warpM = warp & 3;
    const int warpN = warp >> 2;
    const int bx = blockIdx.x, by = blockIdx.y;
    const int kbeg = blockIdx.z * (K >> 1);
    float* Cz = Cp + (size_t)blockIdx.z * M * N;

    const __nv_bfloat16* gA[2] = { Ah + (size_t)(by * 128) * K,
                                   Al + (size_t)(by * 128) * K };
    const __nv_bfloat16* gB[2] = { Bh + (size_t)(bx * 128) * K,
                                   Bl + (size_t)(bx * 128) * K };

    float acc[2][8][4];
    #pragma unroll
    for (int i = 0; i < 2; i++)
        #pragma unroll
        for (int j = 0; j < 8; j++)
            #pragma unroll
            for (int q = 0; q < 4; q++) acc[i][j][q] = 0.f;

    auto issue = [&](int s, int k0) {
        uint32_t stb = sbase + s * STAGE_B;
        #pragma unroll
        for (int t = 0; t < 8; t++) {
            const int tile = t >> 1;
            int w = ((t & 1) << 8) + tid;
            int r = w >> 2, seg = w & 3;
            int sw = seg ^ ((r >> 1) & 3);
            uint32_t dst = stb + tile * TILE_B + r * 64 + sw * 16;
            const __nv_bfloat16* src =
                (tile == 0 ? gA[0] : tile == 1 ? gA[1] : tile == 2 ? gB[0] : gB[1])
                + (size_t)r * K + k0 + seg * 8;
            CP_ASYNC16(dst, src);
        }
    };

    const int frow = lane & 15;
    const int fku  = lane >> 4;

    auto compute = [&](int s) {
        uint32_t stb = sbase + s * STAGE_B;
        #pragma unroll
        for (int ks = 0; ks < 2; ks++) {
            uint32_t ah[2][4], al[2][4];
            #pragma unroll
            for (int mi = 0; mi < 2; mi++) {
                int R = warpM * 32 + mi * 16 + frow;
                int u = (ks * 2 + fku) ^ ((R >> 1) & 3);
                uint32_t ad = stb + (uint32_t)(R * 64 + u * 16);
                ldmx4(ad, ah[mi][0], ah[mi][1], ah[mi][2], ah[mi][3]);
                ldmx4(ad + TILE_B, al[mi][0], al[mi][1], al[mi][2], al[mi][3]);
            }
            #pragma unroll
            for (int np = 0; np < 4; np++) {
                uint32_t bh4[4], bl4[4];
                int R = warpN * 64 + np * 16 + frow;
                int u = (ks * 2 + fku) ^ ((R >> 1) & 3);
                uint32_t bd = stb + 2 * TILE_B + (uint32_t)(R * 64 + u * 16);
                ldmx4(bd, bh4[0], bh4[1], bh4[2], bh4[3]);
                ldmx4(bd + TILE_B, bl4[0], bl4[1], bl4[2], bl4[3]);
                mma16816(acc[0][2*np],   ah[0], bh4[0], bh4[2]);
                mma16816(acc[1][2*np],   ah[1], bh4[0], bh4[2]);
                mma16816(acc[0][2*np+1], ah[0], bh4[1], bh4[3]);
                mma16816(acc[1][2*np+1], ah[1], bh4[1], bh4[3]);
                mma16816(acc[0][2*np],   ah[0], bl4[0], bl4[2]);
                mma16816(acc[1][2*np],   ah[1], bl4[0], bl4[2]);
                mma16816(acc[0][2*np+1], ah[0], bl4[1], bl4[3]);
                mma16816(acc[1][2*np+1], ah[1], bl4[1], bl4[3]);
                mma16816(acc[0][2*np],   al[0], bh4[0], bh4[2]);
                mma16816(acc[1][2*np],   al[1], bh4[0], bh4[2]);
                mma16816(acc[0][2*np+1], al[0], bh4[1], bh4[3]);
                mma16816(acc[1][2*np+1], al[1], bh4[1], bh4[3]);
            }
        }
    };

    const int nch = (K >> 1) >> 5;
    issue(0, kbeg);
    CP_COMMIT();
    issue(1, kbeg + 32);
    CP_COMMIT();
    int sc = 0, si = 2;
    for (int c = 0; c < nch; c++) {
        CP_WAIT1();
        __syncthreads();
        if (c + 2 < nch) {
            issue(si, kbeg + ((c + 2) << 5));
            CP_COMMIT();
            if (++si == 3) si = 0;
        }
        compute(sc);
        if (++sc == 3) sc = 0;
    }

    const int tr = lane >> 2;
    const int tc = (lane & 3) * 2;
    const int grow0 = by * 128 + warpM * 32;
    const int gcol0 = bx * 128 + warpN * 64;
    #pragma unroll
    for (int mi = 0; mi < 2; mi++) {
        #pragma unroll
        for (int ni = 0; ni < 8; ni++) {
            int col = gcol0 + ni * 8 + tc;
            #pragma unroll
            for (int half = 0; half < 2; half++) {
                int row = grow0 + mi * 16 + tr + half * 8;
                *(float2*)(Cz + (size_t)row * N + col) =
                    make_float2(acc[mi][ni][half * 2 + 0], acc[mi][ni][half * 2 + 1]);
            }
        }
    }
}

// ---------------- split-K reduce: x += p0 + p1 + bias (N = Dq) --------------
__global__ __launch_bounds__(256) void skred_kernel(const float* __restrict__ p,
                                                    const float* __restrict__ bias,
                                                    float* __restrict__ x) {
    size_t i = (size_t)blockIdx.x * 256 + threadIdx.x;
    const float4 a = ((const float4*)p)[i];
    const float4 b2 = ((const float4*)p)[i + (size_t)BSq * Dq / 4];
    const float4 bv = ((const float4*)bias)[i & (Dq / 4 - 1)];
    float4 xv = ((float4*)x)[i];
    xv.x += a.x + b2.x + bv.x;
    xv.y += a.y + b2.y + bv.y;
    xv.z += a.z + b2.z + bv.z;
    xv.w += a.w + b2.w + bv.w;
    ((float4*)x)[i] = xv;
}

// ---------- split-K reduce + GELU + bf16 hi/lo split (N = D4q) --------------
__global__ __launch_bounds__(256) void skredg_kernel(const float* __restrict__ p,
                                                     const float* __restrict__ bias,
                                                     __nv_bfloat16* __restrict__ mh,
                                                     __nv_bfloat16* __restrict__ ml) {
    size_t i = (size_t)blockIdx.x * 256 + threadIdx.x;   // float4 idx over BSq*D4q/4
    const float4 a  = ((const float4*)p)[i];
    const float4 b2 = ((const float4*)p)[i + (size_t)BSq * D4q / 4];
    const float4 bv = ((const float4*)bias)[i & (D4q / 4 - 1)];
    float v0 = a.x + b2.x + bv.x;
    float v1 = a.y + b2.y + bv.y;
    float v2 = a.z + b2.z + bv.z;
    float v3 = a.w + b2.w + bv.w;
    v0 = 0.5f * v0 * (1.0f + erff(v0 * 0.70710678118654752f));
    v1 = 0.5f * v1 * (1.0f + erff(v1 * 0.70710678118654752f));
    v2 = 0.5f * v2 * (1.0f + erff(v2 * 0.70710678118654752f));
    v3 = 0.5f * v3 * (1.0f + erff(v3 * 0.70710678118654752f));
    __nv_bfloat16 h0 = __float2bfloat16(v0);
    __nv_bfloat16 h1 = __float2bfloat16(v1);
    __nv_bfloat16 h2 = __float2bfloat16(v2);
    __nv_bfloat16 h3 = __float2bfloat16(v3);
    size_t off = i * 4;
    *(__nv_bfloat162*)(mh + off)     = __nv_bfloat162(h0, h1);
    *(__nv_bfloat162*)(mh + off + 2) = __nv_bfloat162(h2, h3);
    *(__nv_bfloat162*)(ml + off)     = __nv_bfloat162(
        __float2bfloat16(v0 - __bfloat162float(h0)),
        __float2bfloat16(v1 - __bfloat162float(h1)));
    *(__nv_bfloat162*)(ml + off + 2) = __nv_bfloat162(
        __float2bfloat16(v2 - __bfloat162float(h2)),
        __float2bfloat16(v3 - __bfloat162float(h3)));
}

// ---------------- flash attention (HMMA, hi/lo, online softmax) -------------
__global__ __launch_bounds__(128) void flash_kernel(const __nv_bfloat16* __restrict__ qh,
                                                    const __nv_bfloat16* __restrict__ ql,
                                                    __nv_bfloat16* __restrict__ oh,
                                                    __nv_bfloat16* __restrict__ ol) {
    __shared__ __nv_bfloat16 sm[4][64][72];
    const int qt = blockIdx.x, z = blockIdx.y;
    const int b = z >> 4, h = z & 15;
    const int tid = threadIdx.x, lane = tid & 31, warp = tid >> 5;
    const int frow = lane & 15, fko = (lane >> 4) << 3;
    const int tr = lane >> 2, tc = lane & 3;

    const size_t qrowbase = (size_t)(b * Sq + qt * 64);

    for (int i = tid; i < 512; i += 128) {
        int r = i >> 3, s = i & 7;
        size_t g = (qrowbase + r) * D3q + h * 64 + s * 8;
        *(uint4*)&sm[0][r][s * 8] = *(const uint4*)(qh + g);
        *(uint4*)&sm[1][r][s * 8] = *(const uint4*)(ql + g);
    }
    __syncthreads();
    uint32_t qfh[4][4], qfl[4][4];
    #pragma unroll
    for (int kc = 0; kc < 4; kc++) {
        ldmx4(smem_u32(&sm[0][warp * 16 + frow][kc * 16 + fko]),
              qfh[kc][0], qfh[kc][1], qfh[kc][2], qfh[kc][3]);
        ldmx4(smem_u32(&sm[1][warp * 16 + frow][kc * 16 + fko]),
              qfl[kc][0], qfl[kc][1], qfl[kc][2], qfl[kc][3]);
    }
    __syncthreads();

    float m0 = -1e30f, m1 = -1e30f, l0 = 0.f, l1 = 0.f;
    float oa[8][4];
    #pragma unroll
    for (int i = 0; i < 8; i++)
        #pragma unroll
        for (int j = 0; j < 4; j++) oa[i][j] = 0.f;

    for (int kt = 0; kt <= qt; kt++) {
        const size_t krowbase = (size_t)(b * Sq + kt * 64);
        for (int i = tid; i < 512; i += 128) {
            int r = i >> 3, s = i & 7;
            size_t gk = (krowbase + r) * D3q + Dq + h * 64 + s * 8;
            size_t gv = (krowbase + r) * D3q + 2 * Dq + h * 64 + s * 8;
            *(uint4*)&sm[0][r][s * 8] = *(const uint4*)(qh + gk);
            *(uint4*)&sm[1][r][s * 8] = *(const uint4*)(ql + gk);
            *(uint4*)&sm[2][r][s * 8] = *(const uint4*)(qh + gv);
            *(uint4*)&sm[3][r][s * 8] = *(const uint4*)(ql + gv);
        }
        __syncthreads();

        float c[8][4];
        #pragma unroll
        for (int i = 0; i < 8; i++)
            #pragma unroll
            for (int j = 0; j < 4; j++) c[i][j] = 0.f;
        #pragma unroll
        for (int kc = 0; kc < 4; kc++) {
            #pragma unroll
            for (int np = 0; np < 4; np++) {
                uint32_t kb[4], kl[4];
                ldmx4(smem_u32(&sm[0][np * 16 + frow][kc * 16 + fko]),
                      kb[0], kb[1], kb[2], kb[3]);
                ldmx4(smem_u32(&sm[1][np * 16 + frow][kc * 16 + fko]),
                      kl[0], kl[1], kl[2], kl[3]);
                mma16816(c[2 * np],     qfh[kc], kb[0], kb[2]);
                mma16816(c[2 * np + 1], qfh[kc], kb[1], kb[3]);
                mma16816(c[2 * np],     qfh[kc], kl[0], kl[2]);
                mma16816(c[2 * np + 1], qfh[kc], kl[1], kl[3]);
                mma16816(c[2 * np],     qfl[kc], kb[0], kb[2]);
                mma16816(c[2 * np + 1], qfl[kc], kb[1], kb[3]);
            }
        }
        #pragma unroll
        for (int nt = 0; nt < 8; nt++)
            #pragma unroll
            for (int e = 0; e < 4; e++) c[nt][e] *= SCALEq;
        if (kt == qt) {
            int row0 = qt * 64 + warp * 16 + tr;
            #pragma unroll
            for (int nt = 0; nt < 8; nt++)
                #pragma unroll
                for (int e = 0; e < 4; e++) {
                    int col = kt * 64 + nt * 8 + tc * 2 + (e & 1);
                    int row = row0 + (e >> 1) * 8;
                    if (col > row) c[nt][e] = -1e30f;
                }
        }
        float r0 = -1e30f, r1 = -1e30f;
        #pragma unroll
        for (int nt = 0; nt < 8; nt++) {
            r0 = fmaxf(r0, fmaxf(c[nt][0], c[nt][1]));
            r1 = fmaxf(r1, fmaxf(c[nt][2], c[nt][3]));
        }
        r0 = fmaxf(r0, __shfl_xor_sync(0xffffffffu, r0, 1));
        r0 = fmaxf(r0, __shfl_xor_sync(0xffffffffu, r0, 2));
        r1 = fmaxf(r1, __shfl_xor_sync(0xffffffffu, r1, 1));
        r1 = fmaxf(r1, __shfl_xor_sync(0xffffffffu, r1, 2));
        float mn0 = fmaxf(m0, r0), mn1 = fmaxf(m1, r1);
        float al0 = __expf(m0 - mn0), al1 = __expf(m1 - mn1);
        float s0 = 0.f, s1 = 0.f;
        #pragma unroll
        for (int nt = 0; nt < 8; nt++) {
            c[nt][0] = __expf(c[nt][0] - mn0); s0 += c[nt][0];
            c[nt][1] = __expf(c[nt][1] - mn0); s0 += c[nt][1];
            c[nt][2] = __expf(c[nt][2] - mn1); s1 += c[nt][2];
            c[nt][3] = __expf(c[nt][3] - mn1); s1 += c[nt][3];
        }
        s0 += __shfl_xor_sync(0xffffffffu, s0, 1);
        s0 += __shfl_xor_sync(0xffffffffu, s0, 2);
        s1 += __shfl_xor_sync(0xffffffffu, s1, 1);
        s1 += __shfl_xor_sync(0xffffffffu, s1, 2);
        l0 = l0 * al0 + s0;
        l1 = l1 * al1 + s1;
        m0 = mn0;
        m1 = mn1;
        #pragma unroll
        for (int nt = 0; nt < 8; nt++) {
            oa[nt][0] *= al0; oa[nt][1] *= al0;
            oa[nt][2] *= al1; oa[nt][3] *= al1;
        }
        #pragma unroll
        for (int kc = 0; kc < 4; kc++) {
            float p[8] = { c[2*kc][0], c[2*kc][1], c[2*kc][2], c[2*kc][3],
                           c[2*kc+1][0], c[2*kc+1][1], c[2*kc+1][2], c[2*kc+1][3] };
            float phf[8], plf[8];
            #pragma unroll
            for (int e = 0; e < 8; e++) {
                phf[e] = __bfloat162float(__float2bfloat16(p[e]));
                plf[e] = p[e] - phf[e];
            }
            uint32_t ph[4] = { pk2(phf[0], phf[1]), pk2(phf[2], phf[3]),
                               pk2(phf[4], phf[5]), pk2(phf[6], phf[7]) };
            uint32_t pl[4] = { pk2(plf[0], plf[1]), pk2(plf[2], plf[3]),
                               pk2(plf[4], plf[5]), pk2(plf[6], plf[7]) };
            #pragma unroll
            for (int np = 0; np < 4; np++) {
                uint32_t vh4[4], vl4[4];
                ldmx4t(smem_u32(&sm[2][kc * 16 + frow][np * 16 + fko]),
                       vh4[0], vh4[1], vh4[2], vh4[3]);
                ldmx4t(smem_u32(&sm[3][kc * 16 + frow][np * 16 + fko]),
                       vl4[0], vl4[1], vl4[2], vl4[3]);
                mma16816(oa[2 * np],     ph, vh4[0], vh4[1]);
                mma16816(oa[2 * np + 1], ph, vh4[2], vh4[3]);
                mma16816(oa[2 * np],     ph, vl4[0], vl4[1]);
                mma16816(oa[2 * np + 1], ph, vl4[2], vl4[3]);
                mma16816(oa[2 * np],     pl, vh4[0], vh4[1]);
                mma16816(oa[2 * np + 1], pl, vh4[2], vh4[3]);
            }
        }
        __syncthreads();
    }

    float inv0 = 1.0f / l0, inv1 = 1.0f / l1;
    #pragma unroll
    for (int nt = 0; nt < 8; nt++) {
        int col = h * 64 + nt * 8 + tc * 2;
        #pragma unroll
        for (int half = 0; half < 2; half++) {
            size_t row = qrowbase + warp * 16 + tr + half * 8;
            float inv = half ? inv1 : inv0;
            float v0 = oa[nt][half * 2 + 0] * inv;
            float v1 = oa[nt][half * 2 + 1] * inv;
            __nv_bfloat16 h0 = __float2bfloat16(v0);
            __nv_bfloat16 h1 = __float2bfloat16(v1);
            size_t off = row * Dq + col;
            *(__nv_bfloat162*)(oh + off) = __nv_bfloat162(h0, h1);
            *(__nv_bfloat162*)(ol + off) = __nv_bfloat162(
                __float2bfloat16(v0 - __bfloat162float(h0)),
                __float2bfloat16(v1 - __bfloat162float(h1)));
        }
    }
}

// ---------------- block reductions ----------------
__device__ __forceinline__ float blockReduceSum(float val) {
    __shared__ float sh[32];
    int lane = threadIdx.x & 31, wid = threadIdx.x >> 5;
    #pragma unroll
    for (int o = 16; o > 0; o >>= 1) val += __shfl_down_sync(0xffffffffu, val, o);
    if (lane == 0) sh[wid] = val;
    __syncthreads();
    val = (threadIdx.x < (blockDim.x >> 5)) ? sh[lane] : 0.0f;
    if (wid == 0) {
        #pragma unroll
        for (int o = 16; o > 0; o >>= 1) val += __shfl_down_sync(0xffffffffu, val, o);
        if (lane == 0) sh[0] = val;
    }
    __syncthreads();
    float r = sh[0];
    __syncthreads();
    return r;
}

// ---------------- embedding ----------------
__global__ void embed_kernel(const int* __restrict__ tokens,
                             const float* __restrict__ wte,
                             const float* __restrict__ wpe,
                             float* __restrict__ x) {
    size_t i = (size_t)blockIdx.x * blockDim.x + threadIdx.x;
    int row = (int)(i >> 10);
    int d   = (int)(i & 1023);
    int s   = row & (Sq - 1);
    int tok = tokens[row];
    x[i] = wte[(size_t)tok * Dq + d] + wpe[(size_t)s * Dq + d];
}

// ---------------- layernorm -> bf16 hi/lo (vectorized) ----------------
__global__ __launch_bounds__(256) void ln_split_kernel(const float* __restrict__ x,
                                                       const float* __restrict__ g,
                                                       const float* __restrict__ b,
                                                       __nv_bfloat16* __restrict__ ah,
                                                       __nv_bfloat16* __restrict__ al) {
    int row = blockIdx.x;
    int tid = threadIdx.x;
    const float4 xv = *(const float4*)(x + (size_t)row * Dq + tid * 4);
    float s = xv.x + xv.y + xv.z + xv.w;
    float mean = blockReduceSum(s) * (1.0f / Dq);
    float d0 = xv.x - mean, d1 = xv.y - mean, d2 = xv.z - mean, d3 = xv.w - mean;
    float v = d0 * d0 + d1 * d1 + d2 * d2 + d3 * d3;
    float var = blockReduceSum(v) * (1.0f / Dq);
    float inv = rsqrtf(var + 1e-5f);
    const float4 gv = *(const float4*)(g + tid * 4);
    const float4 bv = *(const float4*)(b + tid * 4);
    float y0 = d0 * inv * gv.x + bv.x;
    float y1 = d1 * inv * gv.y + bv.y;
    float y2 = d2 * inv * gv.z + bv.z;
    float y3 = d3 * inv * gv.w + bv.w;
    __nv_bfloat16 h0 = __float2bfloat16(y0);
    __nv_bfloat16 h1 = __float2bfloat16(y1);
    __nv_bfloat16 h2 = __float2bfloat16(y2);
    __nv_bfloat16 h3 = __float2bfloat16(y3);
    size_t off = (size_t)row * Dq + tid * 4;
    *(__nv_bfloat162*)(ah + off)     = __nv_bfloat162(h0, h1);
    *(__nv_bfloat162*)(ah + off + 2) = __nv_bfloat162(h2, h3);
    *(__nv_bfloat162*)(al + off)     = __nv_bfloat162(
        __float2bfloat16(y0 - __bfloat162float(h0)),
        __float2bfloat16(y1 - __bfloat162float(h1)));
    *(__nv_bfloat162*)(al + off + 2) = __nv_bfloat162(
        __float2bfloat16(y2 - __bfloat162float(h2)),
        __float2bfloat16(y3 - __bfloat162float(h3)));
}

__global__ __launch_bounds__(256) void ln_last_kernel(const float* __restrict__ x,
                                                      const float* __restrict__ g,
                                                      const float* __restrict__ b,
                                                      float* __restrict__ out) {
    int bi = blockIdx.x;
    int row = bi * Sq + (Sq - 1);
    const float* xr = x + (size_t)row * Dq;
    float s = 0.f;
    for (int i = threadIdx.x; i < Dq; i += 256) s += xr[i];
    float mean = blockReduceSum(s) * (1.0f / Dq);
    float v = 0.f;
    for (int i = threadIdx.x; i < Dq; i += 256) { float d0 = xr[i] - mean; v += d0 * d0; }
    float var = blockReduceSum(v) * (1.0f / Dq);
    float inv = rsqrtf(var + 1e-5f);
    float* orow = out + (size_t)bi * Dq;
    for (int i = threadIdx.x; i < Dq; i += 256)
        orow[i] = (xr[i] - mean) * inv * g[i] + b[i];
}

// ---------------- head ----------------
__global__ __launch_bounds__(256) void head_kernel(const float* __restrict__ xf,
                                                   const float* __restrict__ w_head,
                                                   float* __restrict__ out) {
    __shared__ float xs[Bq][Dq];
    for (int i = threadIdx.x; i < Bq * Dq; i += 256)
        xs[i >> 10][i & 1023] = xf[i];
    __syncthreads();
    int v = blockIdx.x * 256 + threadIdx.x;
    if (v >= Vq) return;
    float a0 = 0.f, a1 = 0.f, a2 = 0.f, a3 = 0.f;
    #pragma unroll 4
    for (int d = 0; d < Dq; d++) {
        float w = w_head[(size_t)d * Vq + v];
        a0 += xs[0][d] * w;
        a1 += xs[1][d] * w;
        a2 += xs[2][d] * w;
        a3 += xs[3][d] * w;
    }
    out[v]                  = a0;
    out[(size_t)Vq + v]     = a1;
    out[2 * (size_t)Vq + v] = a2;
    out[3 * (size_t)Vq + v] = a3;
}

// ---------------- launch ----------------
extern "C" void kernel_launch(void* const* d_in, const int* in_sizes, int n_in,
                              void* d_out, int out_size) {
    const int*   tokens = (const int*)  d_in[0];
    const float* wte    = (const float*)d_in[1];
    const float* wpe    = (const float*)d_in[2];
    const float* ln1_g  = (const float*)d_in[3];
    const float* ln1_b  = (const float*)d_in[4];
    const float* wqkv   = (const float*)d_in[5];
    const float* bqkv   = (const float*)d_in[6];
    const float* wo     = (const float*)d_in[7];
    const float* bo     = (const float*)d_in[8];
    const float* ln2_g  = (const float*)d_in[9];
    const float* ln2_b  = (const float*)d_in[10];
    const float* w1     = (const float*)d_in[11];
    const float* b1     = (const float*)d_in[12];
    const float* w2     = (const float*)d_in[13];
    const float* b2     = (const float*)d_in[14];
    const float* lnf_g  = (const float*)d_in[15];
    const float* lnf_b  = (const float*)d_in[16];
    const float* w_head = (const float*)d_in[17];

    float *x, *xf, *pt;
    __nv_bfloat16 *ah, *al, *qh, *ql, *ohp, *olp, *mh, *ml, *bh, *bl;
    cudaGetSymbolAddress((void**)&x,   g_x);
    cudaGetSymbolAddress((void**)&xf,  g_xf);
    cudaGetSymbolAddress((void**)&pt,  g_pt);
    cudaGetSymbolAddress((void**)&ah,  g_ah);
    cudaGetSymbolAddress((void**)&al,  g_al);
    cudaGetSymbolAddress((void**)&qh,  g_qh);
    cudaGetSymbolAddress((void**)&ql,  g_ql);
    cudaGetSymbolAddress((void**)&ohp, g_oh);
    cudaGetSymbolAddress((void**)&olp, g_ol);
    cudaGetSymbolAddress((void**)&mh,  g_mh);
    cudaGetSymbolAddress((void**)&ml,  g_ml);
    cudaGetSymbolAddress((void**)&bh,  g_bh);
    cudaGetSymbolAddress((void**)&bl,  g_bl);

    cudaFuncSetAttribute(hmma_gemm<0,1>, cudaFuncAttributeMaxDynamicSharedMemorySize, HM_SMEM);
    cudaFuncSetAttribute(hmma_gemm<1,0>, cudaFuncAttributeMaxDynamicSharedMemorySize, HM_SMEM);
    cudaFuncSetAttribute(hmma_part,      cudaFuncAttributeMaxDynamicSharedMemorySize, HM_SMEM);

    embed_kernel<<<(BSq * Dq) / 256, 256>>>(tokens, wte, wpe, x);

    for (int l = 0; l < Lq; l++) {
        const float* Wqkv = wqkv + (size_t)l * Dq * D3q;
        const float* Bqkv = bqkv + (size_t)l * D3q;
        const float* Wo   = wo   + (size_t)l * Dq * Dq;
        const float* Bo   = bo   + (size_t)l * Dq;
        const float* W1   = w1   + (size_t)l * Dq * D4q;
        const float* B1   = b1   + (size_t)l * D4q;
        const float* W2   = w2   + (size_t)l * D4q * Dq;
        const float* B2   = b2   + (size_t)l * Dq;

        // ---- attention ----
        ln_split_kernel<<<BSq, 256>>>(x, ln1_g + l * Dq, ln1_b + l * Dq, ah, al);
        splitT_kernel<<<dim3(D3q / 32, Dq / 32), 256>>>(Wqkv, bh, bl, Dq, D3q);
        hmma_gemm<0,1><<<dim3(D3q / 128, BSq / 128), 256, HM_SMEM>>>(
            ah, al, bh, bl, Bqkv, nullptr, nullptr, qh, ql, BSq, D3q, Dq);

        flash_kernel<<<dim3(Sq / 64, Bq * Hq), 128>>>(qh, ql, ohp, olp);

        splitT_kernel<<<dim3(Dq / 32, Dq / 32), 256>>>(Wo, bh, bl, Dq, Dq);
        hmma_gemm<1,0><<<dim3(Dq / 128, BSq / 128), 256, HM_SMEM>>>(
            ohp, olp, bh, bl, Bo, x, x, nullptr, nullptr, BSq, Dq, Dq);

        // ---- MLP ----
        ln_split_kernel<<<BSq, 256>>>(x, ln2_g + l * Dq, ln2_b + l * Dq, ah, al);

        // FC1 with split-K=2 + fused GELU + bf16 hi/lo split reduce
        splitT_kernel<<<dim3(D4q / 32, Dq / 32), 256>>>(W1, bh, bl, Dq, D4q);
        hmma_part<<<dim3(D4q / 128, BSq / 128, 2), 256, HM_SMEM>>>(
            ah, al, bh, bl, pt, BSq, D4q, Dq);
        skredg_kernel<<<(BSq * D4q / 4) / 256, 256>>>(pt, B1, mh, ml);

        // FC2 with split-K=2 + fused residual reduce
        splitT_kernel<<<dim3(Dq / 32, D4q / 32), 256>>>(W2, bh, bl, D4q, Dq);
        hmma_part<<<dim3(Dq / 128, BSq / 128, 2), 256, HM_SMEM>>>(
            mh, ml, bh, bl, pt, BSq, Dq, D4q);
        skred_kernel<<<(BSq * Dq / 4) / 256, 256>>>(pt, B2, x);
    }

    ln_last_kernel<<<Bq, 256>>>(x, lnf_g, lnf_b, xf);
    head_kernel<<<(Vq + 255) / 256, 256>>>(xf, w_head, (float*)d_out);
}

// round 15
// speedup vs baseline: 1.0035x; 1.0035x over previous
#include <cuda_runtime.h>
#include <cuda_bf16.h>
#include <math.h>
#include <stdint.h>

// ---------------- problem constants ----------------
#define Bq   4
#define Sq   1024
#define Dq   1024
#define Hq   16
#define Lq   8
#define Vq   50257
#define HDq  64
#define D3q  (3*Dq)
#define D4q  (4*Dq)
#define BSq  (Bq*Sq)
#define SCALEq 0.125f

// ---------------- scratch (device globals) ----------------
__device__ float g_x [(size_t)BSq*Dq];
__device__ float g_xf[Bq*Dq];
__device__ float g_pt[(size_t)2*BSq*Dq];          // split-K fp32 partials (FC2)
__device__ __nv_bfloat16 g_ah[(size_t)BSq*Dq];
__device__ __nv_bfloat16 g_al[(size_t)BSq*Dq];
__device__ __nv_bfloat16 g_qh[(size_t)BSq*D3q];
__device__ __nv_bfloat16 g_ql[(size_t)BSq*D3q];
__device__ __nv_bfloat16 g_oh[(size_t)BSq*Dq];
__device__ __nv_bfloat16 g_ol[(size_t)BSq*Dq];
__device__ __nv_bfloat16 g_mh[(size_t)BSq*D4q];
__device__ __nv_bfloat16 g_ml[(size_t)BSq*D4q];
__device__ __nv_bfloat16 g_bh[(size_t)D4q*Dq];
__device__ __nv_bfloat16 g_bl[(size_t)D4q*Dq];

// ---------------- PTX helpers (sm_80-level, valid on compute_103) ----------
__device__ __forceinline__ uint32_t smem_u32(const void* p) {
    uint32_t a;
    asm("{ .reg .u64 t; cvta.to.shared.u64 t, %1; cvt.u32.u64 %0, t; }" : "=r"(a) : "l"(p));
    return a;
}
#define CP_ASYNC16(dst, src) \
    asm volatile("cp.async.cg.shared.global [%0], [%1], 16;" :: "r"(dst), "l"(src))
#define CP_COMMIT()  asm volatile("cp.async.commit_group;" ::: "memory")
#define CP_WAIT1()   asm volatile("cp.async.wait_group 1;" ::: "memory")
#define CP_WAIT0()   asm volatile("cp.async.wait_group 0;" ::: "memory")

__device__ __forceinline__ void ldmx4(uint32_t addr, uint32_t& r0, uint32_t& r1,
                                      uint32_t& r2, uint32_t& r3) {
    asm volatile("ldmatrix.sync.aligned.m8n8.x4.shared.b16 {%0,%1,%2,%3}, [%4];"
        : "=r"(r0), "=r"(r1), "=r"(r2), "=r"(r3) : "r"(addr));
}
__device__ __forceinline__ void ldmx4t(uint32_t addr, uint32_t& r0, uint32_t& r1,
                                       uint32_t& r2, uint32_t& r3) {
    asm volatile("ldmatrix.sync.aligned.m8n8.x4.trans.shared.b16 {%0,%1,%2,%3}, [%4];"
        : "=r"(r0), "=r"(r1), "=r"(r2), "=r"(r3) : "r"(addr));
}
__device__ __forceinline__ void mma16816(float* c, const uint32_t* a,
                                         uint32_t b0, uint32_t b1) {
    asm volatile("mma.sync.aligned.m16n8k16.row.col.f32.bf16.bf16.f32 "
        "{%0,%1,%2,%3}, {%4,%5,%6,%7}, {%8,%9}, {%0,%1,%2,%3};"
        : "+f"(c[0]), "+f"(c[1]), "+f"(c[2]), "+f"(c[3])
        : "r"(a[0]), "r"(a[1]), "r"(a[2]), "r"(a[3]), "r"(b0), "r"(b1));
}
__device__ __forceinline__ uint32_t pk2(float lo, float hi) {
    uint32_t r;
    asm("cvt.rn.bf16x2.f32 %0, %1, %2;" : "=r"(r) : "f"(hi), "f"(lo));
    return r;
}

// ---------------- transpose + split (vectorized): W [K,N] -> [N,K] hi/lo ----
__global__ __launch_bounds__(256) void splitT_kernel(const float* __restrict__ W,
                                                     __nv_bfloat16* __restrict__ BhT,
                                                     __nv_bfloat16* __restrict__ BlT,
                                                     int K, int N) {
    __shared__ float t[32][33];
    int n0 = blockIdx.x * 32, k0 = blockIdx.y * 32;
    int tid = threadIdx.x;
    {
        int r  = tid >> 3;
        int c4 = tid & 7;
        float4 v = *(const float4*)(W + (size_t)(k0 + r) * N + n0 + c4 * 4);
        t[r][c4 * 4 + 0] = v.x;
        t[r][c4 * 4 + 1] = v.y;
        t[r][c4 * 4 + 2] = v.z;
        t[r][c4 * 4 + 3] = v.w;
    }
    __syncthreads();
    {
        int n = tid >> 3;
        #pragma unroll
        for (int i = 0; i < 2; i++) {
            int kp = (tid & 7) + i * 8;
            int k  = kp * 2;
            float v0 = t[k][n];
            float v1 = t[k + 1][n];
            __nv_bfloat16 h0 = __float2bfloat16(v0);
            __nv_bfloat16 h1 = __float2bfloat16(v1);
            float l0 = v0 - __bfloat162float(h0);
            float l1 = v1 - __bfloat162float(h1);
            size_t off = (size_t)(n0 + n) * K + k0 + k;
            *(__nv_bfloat162*)(BhT + off) = __nv_bfloat162(h0, h1);
            *(__nv_bfloat162*)(BlT + off) =
                __nv_bfloat162(__float2bfloat16(l0), __float2bfloat16(l1));
        }
    }
}

// ---------------- HMMA GEMM (R8/R11-exact body) ------------------------------
#define TILE_B  8192
#define STAGE_B (4*TILE_B)
#define HM_SMEM (3*STAGE_B)

template<int EPI, int OSPLIT>
__global__ __launch_bounds__(256, 2) void hmma_gemm(const __nv_bfloat16* __restrict__ Ah,
                                                    const __nv_bfloat16* __restrict__ Al,
                                                    const __nv_bfloat16* __restrict__ Bh,
                                                    const __nv_bfloat16* __restrict__ Bl,
                                                    const float* __restrict__ bias,
                                                    const float* __restrict__ res,
                                                    float* __restrict__ C,
                                                    __nv_bfloat16* __restrict__ Ch,
                                                    __nv_bfloat16* __restrict__ Cl,
                                                    int M, int N, int K) {
    extern __shared__ char smem[];
    const uint32_t sbase = smem_u32(smem);
    const int tid = threadIdx.x;
    const int lane = tid & 31;
    const int warp = tid >> 5;
    const int warpM = warp & 3;
    const int warpN = warp >> 2;
    const int bx = blockIdx.x, by = blockIdx.y;

    const __nv_bfloat16* gA[2] = { Ah + (size_t)(by * 128) * K,
                                   Al + (size_t)(by * 128) * K };
    const __nv_bfloat16* gB[2] = { Bh + (size_t)(bx * 128) * K,
                                   Bl + (size_t)(bx * 128) * K };

    float acc[2][8][4];
    #pragma unroll
    for (int i = 0; i < 2; i++)
        #pragma unroll
        for (int j = 0; j < 8; j++)
            #pragma unroll
            for (int q = 0; q < 4; q++) acc[i][j][q] = 0.f;

    auto issue = [&](int s, int k0) {
        uint32_t stb = sbase + s * STAGE_B;
        #pragma unroll
        for (int t = 0; t < 8; t++) {
            const int tile = t >> 1;
            int w = ((t & 1) << 8) + tid;
            int r = w >> 2, seg = w & 3;
            int sw = seg ^ ((r >> 1) & 3);
            uint32_t dst = stb + tile * TILE_B + r * 64 + sw * 16;
            const __nv_bfloat16* src =
                (tile == 0 ? gA[0] : tile == 1 ? gA[1] : tile == 2 ? gB[0] : gB[1])
                + (size_t)r * K + k0 + seg * 8;
            CP_ASYNC16(dst, src);
        }
    };

    const int frow = lane & 15;
    const int fku  = lane >> 4;

    auto compute = [&](int s) {
        uint32_t stb = sbase + s * STAGE_B;
        #pragma unroll
        for (int ks = 0; ks < 2; ks++) {
            uint32_t ah[2][4], al[2][4];
            #pragma unroll
            for (int mi = 0; mi < 2; mi++) {
                int R = warpM * 32 + mi * 16 + frow;
                int u = (ks * 2 + fku) ^ ((R >> 1) & 3);
                uint32_t ad = stb + (uint32_t)(R * 64 + u * 16);
                ldmx4(ad, ah[mi][0], ah[mi][1], ah[mi][2], ah[mi][3]);
                ldmx4(ad + TILE_B, al[mi][0], al[mi][1], al[mi][2], al[mi][3]);
            }
            #pragma unroll
            for (int np = 0; np < 4; np++) {
                uint32_t bh4[4], bl4[4];
                int R = warpN * 64 + np * 16 + frow;
                int u = (ks * 2 + fku) ^ ((R >> 1) & 3);
                uint32_t bd = stb + 2 * TILE_B + (uint32_t)(R * 64 + u * 16);
                ldmx4(bd, bh4[0], bh4[1], bh4[2], bh4[3]);
                ldmx4(bd + TILE_B, bl4[0], bl4[1], bl4[2], bl4[3]);
                mma16816(acc[0][2*np],   ah[0], bh4[0], bh4[2]);
                mma16816(acc[1][2*np],   ah[1], bh4[0], bh4[2]);
                mma16816(acc[0][2*np+1], ah[0], bh4[1], bh4[3]);
                mma16816(acc[1][2*np+1], ah[1], bh4[1], bh4[3]);
                mma16816(acc[0][2*np],   ah[0], bl4[0], bl4[2]);
                mma16816(acc[1][2*np],   ah[1], bl4[0], bl4[2]);
                mma16816(acc[0][2*np+1], ah[0], bl4[1], bl4[3]);
                mma16816(acc[1][2*np+1], ah[1], bl4[1], bl4[3]);
                mma16816(acc[0][2*np],   al[0], bh4[0], bh4[2]);
                mma16816(acc[1][2*np],   al[1], bh4[0], bh4[2]);
                mma16816(acc[0][2*np+1], al[0], bh4[1], bh4[3]);
                mma16816(acc[1][2*np+1], al[1], bh4[1], bh4[3]);
            }
        }
    };

    const int nch = K >> 5;
    issue(0, 0);
    CP_COMMIT();
    issue(1, 32);
    CP_COMMIT();
    int sc = 0, si = 2;
    for (int c = 0; c < nch; c++) {
        CP_WAIT1();
        __syncthreads();
        if (c + 2 < nch) {
            issue(si, (c + 2) << 5);
            CP_COMMIT();
            if (++si == 3) si = 0;
        }
        compute(sc);
        if (++sc == 3) sc = 0;
    }

    const int tr = lane >> 2;
    const int tc = (lane & 3) * 2;
    const int grow0 = by * 128 + warpM * 32;
    const int gcol0 = bx * 128 + warpN * 64;
    #pragma unroll
    for (int mi = 0; mi < 2; mi++) {
        #pragma unroll
        for (int ni = 0; ni < 8; ni++) {
            int col = gcol0 + ni * 8 + tc;
            float b0 = bias[col], b1 = bias[col + 1];
            #pragma unroll
            for (int half = 0; half < 2; half++) {
                int row = grow0 + mi * 16 + tr + half * 8;
                float v0 = acc[mi][ni][half * 2 + 0] + b0;
                float v1 = acc[mi][ni][half * 2 + 1] + b1;
                if (EPI == 1) {
                    const float* rp = res + (size_t)row * N + col;
                    v0 += rp[0];
                    v1 += rp[1];
                }
                if (EPI == 2) {
                    v0 = 0.5f * v0 * (1.0f + erff(v0 * 0.70710678118654752f));
                    v1 = 0.5f * v1 * (1.0f + erff(v1 * 0.70710678118654752f));
                }
                if (OSPLIT) {
                    __nv_bfloat16 h0 = __float2bfloat16(v0);
                    __nv_bfloat16 h1 = __float2bfloat16(v1);
                    float l0 = v0 - __bfloat162float(h0);
                    float l1 = v1 - __bfloat162float(h1);
                    size_t off = (size_t)row * N + col;
                    *(__nv_bfloat162*)(Ch + off) = __nv_bfloat162(h0, h1);
                    *(__nv_bfloat162*)(Cl + off) =
                        __nv_bfloat162(__float2bfloat16(l0), __float2bfloat16(l1));
                } else {
                    *(float2*)(C + (size_t)row * N + col) = make_float2(v0, v1);
                }
            }
        }
    }
}

// ---------------- split-K partial GEMM (FC2): Cp[z] = A @ B^T over K/2 ------
__global__ __launch_bounds__(256, 2) void hmma_part(const __nv_bfloat16* __restrict__ Ah,
                                                    const __nv_bfloat16* __restrict__ Al,
                                                    const __nv_bfloat16* __restrict__ Bh,
                                                    const __nv_bfloat16* __restrict__ Bl,
                                                    float* __restrict__ Cp,
                                                    int M, int N, int K) {
    extern __shared__ char smem[];
    const uint32_t sbase = smem_u32(smem);
    const int tid = threadIdx.x;
    const int lane = tid & 31;
    const int warp = tid >> 5;
    const int warpM = warp & 3;
    const int warpN = warp >> 2;
    const int bx = blockIdx.x, by = blockIdx.y;
    const int kbeg = blockIdx.z * (K >> 1);
    float* Cz = Cp + (size_t)blockIdx.z * M * N;

    const __nv_bfloat16* gA[2] = { Ah + (size_t)(by * 128) * K,
                                   Al + (size_t)(by * 128) * K };
    const __nv_bfloat16* gB[2] = { Bh + (size_t)(bx * 128) * K,
                                   Bl + (size_t)(bx * 128) * K };

    float acc[2][8][4];
    #pragma unroll
    for (int i = 0; i < 2; i++)
        #pragma unroll
        for (int j = 0; j < 8; j++)
            #pragma unroll
            for (int q = 0; q < 4; q++) acc[i][j][q] = 0.f;

    auto issue = [&](int s, int k0) {
        uint32_t stb = sbase + s * STAGE_B;
        #pragma unroll
        for (int t = 0; t < 8; t++) {
            const int tile = t >> 1;
            int w = ((t & 1) << 8) + tid;
            int r = w >> 2, seg = w & 3;
            int sw = seg ^ ((r >> 1) & 3);
            uint32_t dst = stb + tile * TILE_B + r * 64 + sw * 16;
            const __nv_bfloat16* src =
                (tile == 0 ? gA[0] : tile == 1 ? gA[1] : tile == 2 ? gB[0] : gB[1])
                + (size_t)r * K + k0 + seg * 8;
            CP_ASYNC16(dst, src);
        }
    };

    const int frow = lane & 15;
    const int fku  = lane >> 4;

    auto compute = [&](int s) {
        uint32_t stb = sbase + s * STAGE_B;
        #pragma unroll
        for (int ks = 0; ks < 2; ks++) {
            uint32_t ah[2][4], al[2][4];
            #pragma unroll
            for (int mi = 0; mi < 2; mi++) {
                int R = warpM * 32 + mi * 16 + frow;
                int u = (ks * 2 + fku) ^ ((R >> 1) & 3);
                uint32_t ad = stb + (uint32_t)(R * 64 + u * 16);
                ldmx4(ad, ah[mi][0], ah[mi][1], ah[mi][2], ah[mi][3]);
                ldmx4(ad + TILE_B, al[mi][0], al[mi][1], al[mi][2], al[mi][3]);
            }
            #pragma unroll
            for (int np = 0; np < 4; np++) {
                uint32_t bh4[4], bl4[4];
                int R = warpN * 64 + np * 16 + frow;
                int u = (ks * 2 + fku) ^ ((R >> 1) & 3);
                uint32_t bd = stb + 2 * TILE_B + (uint32_t)(R * 64 + u * 16);
                ldmx4(bd, bh4[0], bh4[1], bh4[2], bh4[3]);
                ldmx4(bd + TILE_B, bl4[0], bl4[1], bl4[2], bl4[3]);
                mma16816(acc[0][2*np],   ah[0], bh4[0], bh4[2]);
                mma16816(acc[1][2*np],   ah[1], bh4[0], bh4[2]);
                mma16816(acc[0][2*np+1], ah[0], bh4[1], bh4[3]);
                mma16816(acc[1][2*np+1], ah[1], bh4[1], bh4[3]);
                mma16816(acc[0][2*np],   ah[0], bl4[0], bl4[2]);
                mma16816(acc[1][2*np],   ah[1], bl4[0], bl4[2]);
                mma16816(acc[0][2*np+1], ah[0], bl4[1], bl4[3]);
                mma16816(acc[1][2*np+1], ah[1], bl4[1], bl4[3]);
                mma16816(acc[0][2*np],   al[0], bh4[0], bh4[2]);
                mma16816(acc[1][2*np],   al[1], bh4[0], bh4[2]);
                mma16816(acc[0][2*np+1], al[0], bh4[1], bh4[3]);
                mma16816(acc[1][2*np+1], al[1], bh4[1], bh4[3]);
            }
        }
    };

    const int nch = (K >> 1) >> 5;
    issue(0, kbeg);
    CP_COMMIT();
    issue(1, kbeg + 32);
    CP_COMMIT();
    int sc = 0, si = 2;
    for (int c = 0; c < nch; c++) {
        CP_WAIT1();
        __syncthreads();
        if (c + 2 < nch) {
            issue(si, kbeg + ((c + 2) << 5));
            CP_COMMIT();
            if (++si == 3) si = 0;
        }
        compute(sc);
        if (++sc == 3) sc = 0;
    }

    const int tr = lane >> 2;
    const int tc = (lane & 3) * 2;
    const int grow0 = by * 128 + warpM * 32;
    const int gcol0 = bx * 128 + warpN * 64;
    #pragma unroll
    for (int mi = 0; mi < 2; mi++) {
        #pragma unroll
        for (int ni = 0; ni < 8; ni++) {
            int col = gcol0 + ni * 8 + tc;
            #pragma unroll
            for (int half = 0; half < 2; half++) {
                int row = grow0 + mi * 16 + tr + half * 8;
                *(float2*)(Cz + (size_t)row * N + col) =
                    make_float2(acc[mi][ni][half * 2 + 0], acc[mi][ni][half * 2 + 1]);
            }
        }
    }
}

// ---------------- split-K reduce: x += p0 + p1 + bias (N = Dq) --------------
__global__ __launch_bounds__(256) void skred_kernel(const float* __restrict__ p,
                                                    const float* __restrict__ bias,
                                                    float* __restrict__ x) {
    size_t i = (size_t)blockIdx.x * 256 + threadIdx.x;
    const float4 a = ((const float4*)p)[i];
    const float4 b2 = ((const float4*)p)[i + (size_t)BSq * Dq / 4];
    const float4 bv = ((const float4*)bias)[i & (Dq / 4 - 1)];
    float4 xv = ((float4*)x)[i];
    xv.x += a.x + b2.x + bv.x;
    xv.y += a.y + b2.y + bv.y;
    xv.z += a.z + b2.z + bv.z;
    xv.w += a.w + b2.w + bv.w;
    ((float4*)x)[i] = xv;
}

// ---------------- flash attention (HMMA, hi/lo, online softmax) -------------
// longest-first launch order: qt = (S/64-1) - blockIdx.x (LPT scheduling)
__global__ __launch_bounds__(128) void flash_kernel(const __nv_bfloat16* __restrict__ qh,
                                                    const __nv_bfloat16* __restrict__ ql,
                                                    __nv_bfloat16* __restrict__ oh,
                                                    __nv_bfloat16* __restrict__ ol) {
    __shared__ __nv_bfloat16 sm[4][64][72];
    const int qt = (Sq / 64 - 1) - blockIdx.x;
    const int z = blockIdx.y;
    const int b = z >> 4, h = z & 15;
    const int tid = threadIdx.x, lane = tid & 31, warp = tid >> 5;
    const int frow = lane & 15, fko = (lane >> 4) << 3;
    const int tr = lane >> 2, tc = lane & 3;

    const size_t qrowbase = (size_t)(b * Sq + qt * 64);

    for (int i = tid; i < 512; i += 128) {
        int r = i >> 3, s = i & 7;
        size_t g = (qrowbase + r) * D3q + h * 64 + s * 8;
        *(uint4*)&sm[0][r][s * 8] = *(const uint4*)(qh + g);
        *(uint4*)&sm[1][r][s * 8] = *(const uint4*)(ql + g);
    }
    __syncthreads();
    uint32_t qfh[4][4], qfl[4][4];
    #pragma unroll
    for (int kc = 0; kc < 4; kc++) {
        ldmx4(smem_u32(&sm[0][warp * 16 + frow][kc * 16 + fko]),
              qfh[kc][0], qfh[kc][1], qfh[kc][2], qfh[kc][3]);
        ldmx4(smem_u32(&sm[1][warp * 16 + frow][kc * 16 + fko]),
              qfl[kc][0], qfl[kc][1], qfl[kc][2], qfl[kc][3]);
    }
    __syncthreads();

    float m0 = -1e30f, m1 = -1e30f, l0 = 0.f, l1 = 0.f;
    float oa[8][4];
    #pragma unroll
    for (int i = 0; i < 8; i++)
        #pragma unroll
        for (int j = 0; j < 4; j++) oa[i][j] = 0.f;

    for (int kt = 0; kt <= qt; kt++) {
        const size_t krowbase = (size_t)(b * Sq + kt * 64);
        for (int i = tid; i < 512; i += 128) {
            int r = i >> 3, s = i & 7;
            size_t gk = (krowbase + r) * D3q + Dq + h * 64 + s * 8;
            size_t gv = (krowbase + r) * D3q + 2 * Dq + h * 64 + s * 8;
            *(uint4*)&sm[0][r][s * 8] = *(const uint4*)(qh + gk);
            *(uint4*)&sm[1][r][s * 8] = *(const uint4*)(ql + gk);
            *(uint4*)&sm[2][r][s * 8] = *(const uint4*)(qh + gv);
            *(uint4*)&sm[3][r][s * 8] = *(const uint4*)(ql + gv);
        }
        __syncthreads();

        float c[8][4];
        #pragma unroll
        for (int i = 0; i < 8; i++)
            #pragma unroll
            for (int j = 0; j < 4; j++) c[i][j] = 0.f;
        #pragma unroll
        for (int kc = 0; kc < 4; kc++) {
            #pragma unroll
            for (int np = 0; np < 4; np++) {
                uint32_t kb[4], kl[4];
                ldmx4(smem_u32(&sm[0][np * 16 + frow][kc * 16 + fko]),
                      kb[0], kb[1], kb[2], kb[3]);
                ldmx4(smem_u32(&sm[1][np * 16 + frow][kc * 16 + fko]),
                      kl[0], kl[1], kl[2], kl[3]);
                mma16816(c[2 * np],     qfh[kc], kb[0], kb[2]);
                mma16816(c[2 * np + 1], qfh[kc], kb[1], kb[3]);
                mma16816(c[2 * np],     qfh[kc], kl[0], kl[2]);
                mma16816(c[2 * np + 1], qfh[kc], kl[1], kl[3]);
                mma16816(c[2 * np],     qfl[kc], kb[0], kb[2]);
                mma16816(c[2 * np + 1], qfl[kc], kb[1], kb[3]);
            }
        }
        #pragma unroll
        for (int nt = 0; nt < 8; nt++)
            #pragma unroll
            for (int e = 0; e < 4; e++) c[nt][e] *= SCALEq;
        if (kt == qt) {
            int row0 = qt * 64 + warp * 16 + tr;
            #pragma unroll
            for (int nt = 0; nt < 8; nt++)
                #pragma unroll
                for (int e = 0; e < 4; e++) {
                    int col = kt * 64 + nt * 8 + tc * 2 + (e & 1);
                    int row = row0 + (e >> 1) * 8;
                    if (col > row) c[nt][e] = -1e30f;
                }
        }
        float r0 = -1e30f, r1 = -1e30f;
        #pragma unroll
        for (int nt = 0; nt < 8; nt++) {
            r0 = fmaxf(r0, fmaxf(c[nt][0], c[nt][1]));
            r1 = fmaxf(r1, fmaxf(c[nt][2], c[nt][3]));
        }
        r0 = fmaxf(r0, __shfl_xor_sync(0xffffffffu, r0, 1));
        r0 = fmaxf(r0, __shfl_xor_sync(0xffffffffu, r0, 2));
        r1 = fmaxf(r1, __shfl_xor_sync(0xffffffffu, r1, 1));
        r1 = fmaxf(r1, __shfl_xor_sync(0xffffffffu, r1, 2));
        float mn0 = fmaxf(m0, r0), mn1 = fmaxf(m1, r1);
        float al0 = __expf(m0 - mn0), al1 = __expf(m1 - mn1);
        float s0 = 0.f, s1 = 0.f;
        #pragma unroll
        for (int nt = 0; nt < 8; nt++) {
            c[nt][0] = __expf(c[nt][0] - mn0); s0 += c[nt][0];
            c[nt][1] = __expf(c[nt][1] - mn0); s0 += c[nt][1];
            c[nt][2] = __expf(c[nt][2] - mn1); s1 += c[nt][2];
            c[nt][3] = __expf(c[nt][3] - mn1); s1 += c[nt][3];
        }
        s0 += __shfl_xor_sync(0xffffffffu, s0, 1);
        s0 += __shfl_xor_sync(0xffffffffu, s0, 2);
        s1 += __shfl_xor_sync(0xffffffffu, s1, 1);
        s1 += __shfl_xor_sync(0xffffffffu, s1, 2);
        l0 = l0 * al0 + s0;
        l1 = l1 * al1 + s1;
        m0 = mn0;
        m1 = mn1;
        #pragma unroll
        for (int nt = 0; nt < 8; nt++) {
            oa[nt][0] *= al0; oa[nt][1] *= al0;
            oa[nt][2] *= al1; oa[nt][3] *= al1;
        }
        #pragma unroll
        for (int kc = 0; kc < 4; kc++) {
            float p[8] = { c[2*kc][0], c[2*kc][1], c[2*kc][2], c[2*kc][3],
                           c[2*kc+1][0], c[2*kc+1][1], c[2*kc+1][2], c[2*kc+1][3] };
            float phf[8], plf[8];
            #pragma unroll
            for (int e = 0; e < 8; e++) {
                phf[e] = __bfloat162float(__float2bfloat16(p[e]));
                plf[e] = p[e] - phf[e];
            }
            uint32_t ph[4] = { pk2(phf[0], phf[1]), pk2(phf[2], phf[3]),
                               pk2(phf[4], phf[5]), pk2(phf[6], phf[7]) };
            uint32_t pl[4] = { pk2(plf[0], plf[1]), pk2(plf[2], plf[3]),
                               pk2(plf[4], plf[5]), pk2(plf[6], plf[7]) };
            #pragma unroll
            for (int np = 0; np < 4; np++) {
                uint32_t vh4[4], vl4[4];
                ldmx4t(smem_u32(&sm[2][kc * 16 + frow][np * 16 + fko]),
                       vh4[0], vh4[1], vh4[2], vh4[3]);
                ldmx4t(smem_u32(&sm[3][kc * 16 + frow][np * 16 + fko]),
                       vl4[0], vl4[1], vl4[2], vl4[3]);
                mma16816(oa[2 * np],     ph, vh4[0], vh4[1]);
                mma16816(oa[2 * np + 1], ph, vh4[2], vh4[3]);
                mma16816(oa[2 * np],     ph, vl4[0], vl4[1]);
                mma16816(oa[2 * np + 1], ph, vl4[2], vl4[3]);
                mma16816(oa[2 * np],     pl, vh4[0], vh4[1]);
                mma16816(oa[2 * np + 1], pl, vh4[2], vh4[3]);
            }
        }
        __syncthreads();
    }

    float inv0 = 1.0f / l0, inv1 = 1.0f / l1;
    #pragma unroll
    for (int nt = 0; nt < 8; nt++) {
        int col = h * 64 + nt * 8 + tc * 2;
        #pragma unroll
        for (int half = 0; half < 2; half++) {
            size_t row = qrowbase + warp * 16 + tr + half * 8;
            float inv = half ? inv1 : inv0;
            float v0 = oa[nt][half * 2 + 0] * inv;
            float v1 = oa[nt][half * 2 + 1] * inv;
            __nv_bfloat16 h0 = __float2bfloat16(v0);
            __nv_bfloat16 h1 = __float2bfloat16(v1);
            size_t off = row * Dq + col;
            *(__nv_bfloat162*)(oh + off) = __nv_bfloat162(h0, h1);
            *(__nv_bfloat162*)(ol + off) = __nv_bfloat162(
                __float2bfloat16(v0 - __bfloat162float(h0)),
                __float2bfloat16(v1 - __bfloat162float(h1)));
        }
    }
}

// ---------------- block reductions ----------------
__device__ __forceinline__ float blockReduceSum(float val) {
    __shared__ float sh[32];
    int lane = threadIdx.x & 31, wid = threadIdx.x >> 5;
    #pragma unroll
    for (int o = 16; o > 0; o >>= 1) val += __shfl_down_sync(0xffffffffu, val, o);
    if (lane == 0) sh[wid] = val;
    __syncthreads();
    val = (threadIdx.x < (blockDim.x >> 5)) ? sh[lane] : 0.0f;
    if (wid == 0) {
        #pragma unroll
        for (int o = 16; o > 0; o >>= 1) val += __shfl_down_sync(0xffffffffu, val, o);
        if (lane == 0) sh[0] = val;
    }
    __syncthreads();
    float r = sh[0];
    __syncthreads();
    return r;
}

// ---------------- embedding ----------------
__global__ void embed_kernel(const int* __restrict__ tokens,
                             const float* __restrict__ wte,
                             const float* __restrict__ wpe,
                             float* __restrict__ x) {
    size_t i = (size_t)blockIdx.x * blockDim.x + threadIdx.x;
    int row = (int)(i >> 10);
    int d   = (int)(i & 1023);
    int s   = row & (Sq - 1);
    int tok = tokens[row];
    x[i] = wte[(size_t)tok * Dq + d] + wpe[(size_t)s * Dq + d];
}

// ---------------- layernorm -> bf16 hi/lo (vectorized) ----------------
__global__ __launch_bounds__(256) void ln_split_kernel(const float* __restrict__ x,
                                                       const float* __restrict__ g,
                                                       const float* __restrict__ b,
                                                       __nv_bfloat16* __restrict__ ah,
                                                       __nv_bfloat16* __restrict__ al) {
    int row = blockIdx.x;
    int tid = threadIdx.x;
    const float4 xv = *(const float4*)(x + (size_t)row * Dq + tid * 4);
    float s = xv.x + xv.y + xv.z + xv.w;
    float mean = blockReduceSum(s) * (1.0f / Dq);
    float d0 = xv.x - mean, d1 = xv.y - mean, d2 = xv.z - mean, d3 = xv.w - mean;
    float v = d0 * d0 + d1 * d1 + d2 * d2 + d3 * d3;
    float var = blockReduceSum(v) * (1.0f / Dq);
    float inv = rsqrtf(var + 1e-5f);
    const float4 gv = *(const float4*)(g + tid * 4);
    const float4 bv = *(const float4*)(b + tid * 4);
    float y0 = d0 * inv * gv.x + bv.x;
    float y1 = d1 * inv * gv.y + bv.y;
    float y2 = d2 * inv * gv.z + bv.z;
    float y3 = d3 * inv * gv.w + bv.w;
    __nv_bfloat16 h0 = __float2bfloat16(y0);
    __nv_bfloat16 h1 = __float2bfloat16(y1);
    __nv_bfloat16 h2 = __float2bfloat16(y2);
    __nv_bfloat16 h3 = __float2bfloat16(y3);
    size_t off = (size_t)row * Dq + tid * 4;
    *(__nv_bfloat162*)(ah + off)     = __nv_bfloat162(h0, h1);
    *(__nv_bfloat162*)(ah + off + 2) = __nv_bfloat162(h2, h3);
    *(__nv_bfloat162*)(al + off)     = __nv_bfloat162(
        __float2bfloat16(y0 - __bfloat162float(h0)),
        __float2bfloat16(y1 - __bfloat162float(h1)));
    *(__nv_bfloat162*)(al + off + 2) = __nv_bfloat162(
        __float2bfloat16(y2 - __bfloat162float(h2)),
        __float2bfloat16(y3 - __bfloat162float(h3)));
}

__global__ __launch_bounds__(256) void ln_last_kernel(const float* __restrict__ x,
                                                      const float* __restrict__ g,
                                                      const float* __restrict__ b,
                                                      float* __restrict__ out) {
    int bi = blockIdx.x;
    int row = bi * Sq + (Sq - 1);
    const float* xr = x + (size_t)row * Dq;
    float s = 0.f;
    for (int i = threadIdx.x; i < Dq; i += 256) s += xr[i];
    float mean = blockReduceSum(s) * (1.0f / Dq);
    float v = 0.f;
    for (int i = threadIdx.x; i < Dq; i += 256) { float d0 = xr[i] - mean; v += d0 * d0; }
    float var = blockReduceSum(v) * (1.0f / Dq);
    float inv = rsqrtf(var + 1e-5f);
    float* orow = out + (size_t)bi * Dq;
    for (int i = threadIdx.x; i < Dq; i += 256)
        orow[i] = (xr[i] - mean) * inv * g[i] + b[i];
}

// ---------------- head ----------------
__global__ __launch_bounds__(256) void head_kernel(const float* __restrict__ xf,
                                                   const float* __restrict__ w_head,
                                                   float* __restrict__ out) {
    __shared__ float xs[Bq][Dq];
    for (int i = threadIdx.x; i < Bq * Dq; i += 256)
        xs[i >> 10][i & 1023] = xf[i];
    __syncthreads();
    int v = blockIdx.x * 256 + threadIdx.x;
    if (v >= Vq) return;
    float a0 = 0.f, a1 = 0.f, a2 = 0.f, a3 = 0.f;
    #pragma unroll 4
    for (int d = 0; d < Dq; d++) {
        float w = w_head[(size_t)d * Vq + v];
        a0 += xs[0][d] * w;
        a1 += xs[1][d] * w;
        a2 += xs[2][d] * w;
        a3 += xs[3][d] * w;
    }
    out[v]                  = a0;
    out[(size_t)Vq + v]     = a1;
    out[2 * (size_t)Vq + v] = a2;
    out[3 * (size_t)Vq + v] = a3;
}

// ---------------- launch ----------------
extern "C" void kernel_launch(void* const* d_in, const int* in_sizes, int n_in,
                              void* d_out, int out_size) {
    const int*   tokens = (const int*)  d_in[0];
    const float* wte    = (const float*)d_in[1];
    const float* wpe    = (const float*)d_in[2];
    const float* ln1_g  = (const float*)d_in[3];
    const float* ln1_b  = (const float*)d_in[4];
    const float* wqkv   = (const float*)d_in[5];
    const float* bqkv   = (const float*)d_in[6];
    const float* wo     = (const float*)d_in[7];
    const float* bo     = (const float*)d_in[8];
    const float* ln2_g  = (const float*)d_in[9];
    const float* ln2_b  = (const float*)d_in[10];
    const float* w1     = (const float*)d_in[11];
    const float* b1     = (const float*)d_in[12];
    const float* w2     = (const float*)d_in[13];
    const float* b2     = (const float*)d_in[14];
    const float* lnf_g  = (const float*)d_in[15];
    const float* lnf_b  = (const float*)d_in[16];
    const float* w_head = (const float*)d_in[17];

    float *x, *xf, *pt;
    __nv_bfloat16 *ah, *al, *qh, *ql, *ohp, *olp, *mh, *ml, *bh, *bl;
    cudaGetSymbolAddress((void**)&x,   g_x);
    cudaGetSymbolAddress((void**)&xf,  g_xf);
    cudaGetSymbolAddress((void**)&pt,  g_pt);
    cudaGetSymbolAddress((void**)&ah,  g_ah);
    cudaGetSymbolAddress((void**)&al,  g_al);
    cudaGetSymbolAddress((void**)&qh,  g_qh);
    cudaGetSymbolAddress((void**)&ql,  g_ql);
    cudaGetSymbolAddress((void**)&ohp, g_oh);
    cudaGetSymbolAddress((void**)&olp, g_ol);
    cudaGetSymbolAddress((void**)&mh,  g_mh);
    cudaGetSymbolAddress((void**)&ml,  g_ml);
    cudaGetSymbolAddress((void**)&bh,  g_bh);
    cudaGetSymbolAddress((void**)&bl,  g_bl);

    cudaFuncSetAttribute(hmma_gemm<0,1>, cudaFuncAttributeMaxDynamicSharedMemorySize, HM_SMEM);
    cudaFuncSetAttribute(hmma_gemm<1,0>, cudaFuncAttributeMaxDynamicSharedMemorySize, HM_SMEM);
    cudaFuncSetAttribute(hmma_gemm<2,1>, cudaFuncAttributeMaxDynamicSharedMemorySize, HM_SMEM);
    cudaFuncSetAttribute(hmma_part,      cudaFuncAttributeMaxDynamicSharedMemorySize, HM_SMEM);

    embed_kernel<<<(BSq * Dq) / 256, 256>>>(tokens, wte, wpe, x);

    for (int l = 0; l < Lq; l++) {
        const float* Wqkv = wqkv + (size_t)l * Dq * D3q;
        const float* Bqkv = bqkv + (size_t)l * D3q;
        const float* Wo   = wo   + (size_t)l * Dq * Dq;
        const float* Bo   = bo   + (size_t)l * Dq;
        const float* W1   = w1   + (size_t)l * Dq * D4q;
        const float* B1   = b1   + (size_t)l * D4q;
        const float* W2   = w2   + (size_t)l * D4q * Dq;
        const float* B2   = b2   + (size_t)l * Dq;

        // ---- attention ----
        ln_split_kernel<<<BSq, 256>>>(x, ln1_g + l * Dq, ln1_b + l * Dq, ah, al);
        splitT_kernel<<<dim3(D3q / 32, Dq / 32), 256>>>(Wqkv, bh, bl, Dq, D3q);
        hmma_gemm<0,1><<<dim3(D3q / 128, BSq / 128), 256, HM_SMEM>>>(
            ah, al, bh, bl, Bqkv, nullptr, nullptr, qh, ql, BSq, D3q, Dq);

        flash_kernel<<<dim3(Sq / 64, Bq * Hq), 128>>>(qh, ql, ohp, olp);

        splitT_kernel<<<dim3(Dq / 32, Dq / 32), 256>>>(Wo, bh, bl, Dq, Dq);
        hmma_gemm<1,0><<<dim3(Dq / 128, BSq / 128), 256, HM_SMEM>>>(
            ohp, olp, bh, bl, Bo, x, x, nullptr, nullptr, BSq, Dq, Dq);

        // ---- MLP ----
        ln_split_kernel<<<BSq, 256>>>(x, ln2_g + l * Dq, ln2_b + l * Dq, ah, al);
        splitT_kernel<<<dim3(D4q / 32, Dq / 32), 256>>>(W1, bh, bl, Dq, D4q);
        hmma_gemm<2,1><<<dim3(D4q / 128, BSq / 128), 256, HM_SMEM>>>(
            ah, al, bh, bl, B1, nullptr, nullptr, mh, ml, BSq, D4q, Dq);

        // FC2 with split-K=2 + fused residual reduce
        splitT_kernel<<<dim3(Dq / 32, D4q / 32), 256>>>(W2, bh, bl, D4q, Dq);
        hmma_part<<<dim3(Dq / 128, BSq / 128, 2), 256, HM_SMEM>>>(
            mh, ml, bh, bl, pt, BSq, Dq, D4q);
        skred_kernel<<<(BSq * Dq / 4) / 256, 256>>>(pt, B2, x);
    }

    ln_last_kernel<<<Bq, 256>>>(x, lnf_g, lnf_b, xf);
    head_kernel<<<(Vq + 255) / 256, 256>>>(xf, w_head, (float*)d_out);
}

// round 16
// speedup vs baseline: 1.0102x; 1.0066x over previous
#include <cuda_runtime.h>
#include <cuda_bf16.h>
#include <math.h>
#include <stdint.h>

// ---------------- problem constants ----------------
#define Bq   4
#define Sq   1024
#define Dq   1024
#define Hq   16
#define Lq   8
#define Vq   50257
#define HDq  64
#define D3q  (3*Dq)
#define D4q  (4*Dq)
#define BSq  (Bq*Sq)
#define SCALEq 0.125f

// ---------------- scratch (device globals) ----------------
__device__ float g_x [(size_t)BSq*Dq];
__device__ float g_xf[Bq*Dq];
__device__ float g_pt[(size_t)2*BSq*Dq];          // split-K fp32 partials (FC2)
__device__ __nv_bfloat16 g_ah[(size_t)BSq*Dq];
__device__ __nv_bfloat16 g_al[(size_t)BSq*Dq];
__device__ __nv_bfloat16 g_qh[(size_t)BSq*D3q];
__device__ __nv_bfloat16 g_ql[(size_t)BSq*D3q];
__device__ __nv_bfloat16 g_oh[(size_t)BSq*Dq];
__device__ __nv_bfloat16 g_ol[(size_t)BSq*Dq];
__device__ __nv_bfloat16 g_mh[(size_t)BSq*D4q];
__device__ __nv_bfloat16 g_ml[(size_t)BSq*D4q];
__device__ __nv_bfloat16 g_bh[(size_t)D4q*Dq];
__device__ __nv_bfloat16 g_bl[(size_t)D4q*Dq];

// ---------------- PTX helpers (sm_80-level, valid on compute_103) ----------
__device__ __forceinline__ uint32_t smem_u32(const void* p) {
    uint32_t a;
    asm("{ .reg .u64 t; cvta.to.shared.u64 t, %1; cvt.u32.u64 %0, t; }" : "=r"(a) : "l"(p));
    return a;
}
#define CP_ASYNC16(dst, src) \
    asm volatile("cp.async.cg.shared.global [%0], [%1], 16;" :: "r"(dst), "l"(src))
#define CP_COMMIT()  asm volatile("cp.async.commit_group;" ::: "memory")
#define CP_WAIT1()   asm volatile("cp.async.wait_group 1;" ::: "memory")
#define CP_WAIT0()   asm volatile("cp.async.wait_group 0;" ::: "memory")

__device__ __forceinline__ void ldmx4(uint32_t addr, uint32_t& r0, uint32_t& r1,
                                      uint32_t& r2, uint32_t& r3) {
    asm volatile("ldmatrix.sync.aligned.m8n8.x4.shared.b16 {%0,%1,%2,%3}, [%4];"
        : "=r"(r0), "=r"(r1), "=r"(r2), "=r"(r3) : "r"(addr));
}
__device__ __forceinline__ void ldmx4t(uint32_t addr, uint32_t& r0, uint32_t& r1,
                                       uint32_t& r2, uint32_t& r3) {
    asm volatile("ldmatrix.sync.aligned.m8n8.x4.trans.shared.b16 {%0,%1,%2,%3}, [%4];"
        : "=r"(r0), "=r"(r1), "=r"(r2), "=r"(r3) : "r"(addr));
}
__device__ __forceinline__ void mma16816(float* c, const uint32_t* a,
                                         uint32_t b0, uint32_t b1) {
    asm volatile("mma.sync.aligned.m16n8k16.row.col.f32.bf16.bf16.f32 "
        "{%0,%1,%2,%3}, {%4,%5,%6,%7}, {%8,%9}, {%0,%1,%2,%3};"
        : "+f"(c[0]), "+f"(c[1]), "+f"(c[2]), "+f"(c[3])
        : "r"(a[0]), "r"(a[1]), "r"(a[2]), "r"(a[3]), "r"(b0), "r"(b1));
}
__device__ __forceinline__ uint32_t pk2(float lo, float hi) {
    uint32_t r;
    asm("cvt.rn.bf16x2.f32 %0, %1, %2;" : "=r"(r) : "f"(hi), "f"(lo));
    return r;
}

// ---------------- transpose + split (vectorized): W [K,N] -> [N,K] hi/lo ----
__global__ __launch_bounds__(256) void splitT_kernel(const float* __restrict__ W,
                                                     __nv_bfloat16* __restrict__ BhT,
                                                     __nv_bfloat16* __restrict__ BlT,
                                                     int K, int N) {
    __shared__ float t[32][33];
    int n0 = blockIdx.x * 32, k0 = blockIdx.y * 32;
    int tid = threadIdx.x;
    {
        int r  = tid >> 3;
        int c4 = tid & 7;
        float4 v = *(const float4*)(W + (size_t)(k0 + r) * N + n0 + c4 * 4);
        t[r][c4 * 4 + 0] = v.x;
        t[r][c4 * 4 + 1] = v.y;
        t[r][c4 * 4 + 2] = v.z;
        t[r][c4 * 4 + 3] = v.w;
    }
    __syncthreads();
    {
        int n = tid >> 3;
        #pragma unroll
        for (int i = 0; i < 2; i++) {
            int kp = (tid & 7) + i * 8;
            int k  = kp * 2;
            float v0 = t[k][n];
            float v1 = t[k + 1][n];
            __nv_bfloat16 h0 = __float2bfloat16(v0);
            __nv_bfloat16 h1 = __float2bfloat16(v1);
            float l0 = v0 - __bfloat162float(h0);
            float l1 = v1 - __bfloat162float(h1);
            size_t off = (size_t)(n0 + n) * K + k0 + k;
            *(__nv_bfloat162*)(BhT + off) = __nv_bfloat162(h0, h1);
            *(__nv_bfloat162*)(BlT + off) =
                __nv_bfloat162(__float2bfloat16(l0), __float2bfloat16(l1));
        }
    }
}

// ---------------- HMMA GEMM (R8/R11-exact body) ------------------------------
#define TILE_B  8192
#define STAGE_B (4*TILE_B)
#define HM_SMEM (3*STAGE_B)

template<int EPI, int OSPLIT>
__global__ __launch_bounds__(256, 2) void hmma_gemm(const __nv_bfloat16* __restrict__ Ah,
                                                    const __nv_bfloat16* __restrict__ Al,
                                                    const __nv_bfloat16* __restrict__ Bh,
                                                    const __nv_bfloat16* __restrict__ Bl,
                                                    const float* __restrict__ bias,
                                                    const float* __restrict__ res,
                                                    float* __restrict__ C,
                                                    __nv_bfloat16* __restrict__ Ch,
                                                    __nv_bfloat16* __restrict__ Cl,
                                                    int M, int N, int K) {
    extern __shared__ char smem[];
    const uint32_t sbase = smem_u32(smem);
    const int tid = threadIdx.x;
    const int lane = tid & 31;
    const int warp = tid >> 5;
    const int warpM = warp & 3;
    const int warpN = warp >> 2;
    const int bx = blockIdx.x, by = blockIdx.y;

    const __nv_bfloat16* gA[2] = { Ah + (size_t)(by * 128) * K,
                                   Al + (size_t)(by * 128) * K };
    const __nv_bfloat16* gB[2] = { Bh + (size_t)(bx * 128) * K,
                                   Bl + (size_t)(bx * 128) * K };

    float acc[2][8][4];
    #pragma unroll
    for (int i = 0; i < 2; i++)
        #pragma unroll
        for (int j = 0; j < 8; j++)
            #pragma unroll
            for (int q = 0; q < 4; q++) acc[i][j][q] = 0.f;

    auto issue = [&](int s, int k0) {
        uint32_t stb = sbase + s * STAGE_B;
        #pragma unroll
        for (int t = 0; t < 8; t++) {
            const int tile = t >> 1;
            int w = ((t & 1) << 8) + tid;
            int r = w >> 2, seg = w & 3;
            int sw = seg ^ ((r >> 1) & 3);
            uint32_t dst = stb + tile * TILE_B + r * 64 + sw * 16;
            const __nv_bfloat16* src =
                (tile == 0 ? gA[0] : tile == 1 ? gA[1] : tile == 2 ? gB[0] : gB[1])
                + (size_t)r * K + k0 + seg * 8;
            CP_ASYNC16(dst, src);
        }
    };

    const int frow = lane & 15;
    const int fku  = lane >> 4;

    auto compute = [&](int s) {
        uint32_t stb = sbase + s * STAGE_B;
        #pragma unroll
        for (int ks = 0; ks < 2; ks++) {
            uint32_t ah[2][4], al[2][4];
            #pragma unroll
            for (int mi = 0; mi < 2; mi++) {
                int R = warpM * 32 + mi * 16 + frow;
                int u = (ks * 2 + fku) ^ ((R >> 1) & 3);
                uint32_t ad = stb + (uint32_t)(R * 64 + u * 16);
                ldmx4(ad, ah[mi][0], ah[mi][1], ah[mi][2], ah[mi][3]);
                ldmx4(ad + TILE_B, al[mi][0], al[mi][1], al[mi][2], al[mi][3]);
            }
            #pragma unroll
            for (int np = 0; np < 4; np++) {
                uint32_t bh4[4], bl4[4];
                int R = warpN * 64 + np * 16 + frow;
                int u = (ks * 2 + fku) ^ ((R >> 1) & 3);
                uint32_t bd = stb + 2 * TILE_B + (uint32_t)(R * 64 + u * 16);
                ldmx4(bd, bh4[0], bh4[1], bh4[2], bh4[3]);
                ldmx4(bd + TILE_B, bl4[0], bl4[1], bl4[2], bl4[3]);
                mma16816(acc[0][2*np],   ah[0], bh4[0], bh4[2]);
                mma16816(acc[1][2*np],   ah[1], bh4[0], bh4[2]);
                mma16816(acc[0][2*np+1], ah[0], bh4[1], bh4[3]);
                mma16816(acc[1][2*np+1], ah[1], bh4[1], bh4[3]);
                mma16816(acc[0][2*np],   ah[0], bl4[0], bl4[2]);
                mma16816(acc[1][2*np],   ah[1], bl4[0], bl4[2]);
                mma16816(acc[0][2*np+1], ah[0], bl4[1], bl4[3]);
                mma16816(acc[1][2*np+1], ah[1], bl4[1], bl4[3]);
                mma16816(acc[0][2*np],   al[0], bh4[0], bh4[2]);
                mma16816(acc[1][2*np],   al[1], bh4[0], bh4[2]);
                mma16816(acc[0][2*np+1], al[0], bh4[1], bh4[3]);
                mma16816(acc[1][2*np+1], al[1], bh4[1], bh4[3]);
            }
        }
    };

    const int nch = K >> 5;
    issue(0, 0);
    CP_COMMIT();
    issue(1, 32);
    CP_COMMIT();
    int sc = 0, si = 2;
    for (int c = 0; c < nch; c++) {
        CP_WAIT1();
        __syncthreads();
        if (c + 2 < nch) {
            issue(si, (c + 2) << 5);
            CP_COMMIT();
            if (++si == 3) si = 0;
        }
        compute(sc);
        if (++sc == 3) sc = 0;
    }

    const int tr = lane >> 2;
    const int tc = (lane & 3) * 2;
    const int grow0 = by * 128 + warpM * 32;
    const int gcol0 = bx * 128 + warpN * 64;
    #pragma unroll
    for (int mi = 0; mi < 2; mi++) {
        #pragma unroll
        for (int ni = 0; ni < 8; ni++) {
            int col = gcol0 + ni * 8 + tc;
            float b0 = bias[col], b1 = bias[col + 1];
            #pragma unroll
            for (int half = 0; half < 2; half++) {
                int row = grow0 + mi * 16 + tr + half * 8;
                float v0 = acc[mi][ni][half * 2 + 0] + b0;
                float v1 = acc[mi][ni][half * 2 + 1] + b1;
                if (EPI == 1) {
                    const float* rp = res + (size_t)row * N + col;
                    v0 += rp[0];
                    v1 += rp[1];
                }
                if (EPI == 2) {
                    v0 = 0.5f * v0 * (1.0f + erff(v0 * 0.70710678118654752f));
                    v1 = 0.5f * v1 * (1.0f + erff(v1 * 0.70710678118654752f));
                }
                if (OSPLIT) {
                    __nv_bfloat16 h0 = __float2bfloat16(v0);
                    __nv_bfloat16 h1 = __float2bfloat16(v1);
                    float l0 = v0 - __bfloat162float(h0);
                    float l1 = v1 - __bfloat162float(h1);
                    size_t off = (size_t)row * N + col;
                    *(__nv_bfloat162*)(Ch + off) = __nv_bfloat162(h0, h1);
                    *(__nv_bfloat162*)(Cl + off) =
                        __nv_bfloat162(__float2bfloat16(l0), __float2bfloat16(l1));
                } else {
                    *(float2*)(C + (size_t)row * N + col) = make_float2(v0, v1);
                }
            }
        }
    }
}

// ---------------- split-K partial GEMM (FC2): Cp[z] = A @ B^T over K/2 ------
__global__ __launch_bounds__(256, 2) void hmma_part(const __nv_bfloat16* __restrict__ Ah,
                                                    const __nv_bfloat16* __restrict__ Al,
                                                    const __nv_bfloat16* __restrict__ Bh,
                                                    const __nv_bfloat16* __restrict__ Bl,
                                                    float* __restrict__ Cp,
                                                    int M, int N, int K) {
    extern __shared__ char smem[];
    const uint32_t sbase = smem_u32(smem);
    const int tid = threadIdx.x;
    const int lane = tid & 31;
    const int warp = tid >> 5;
    const int warpM = warp & 3;
    const int warpN = warp >> 2;
    const int bx = blockIdx.x, by = blockIdx.y;
    const int kbeg = blockIdx.z * (K >> 1);
    float* Cz = Cp + (size_t)blockIdx.z * M * N;

    const __nv_bfloat16* gA[2] = { Ah + (size_t)(by * 128) * K,
                                   Al + (size_t)(by * 128) * K };
    const __nv_bfloat16* gB[2] = { Bh + (size_t)(bx * 128) * K,
                                   Bl + (size_t)(bx * 128) * K };

    float acc[2][8][4];
    #pragma unroll
    for (int i = 0; i < 2; i++)
        #pragma unroll
        for (int j = 0; j < 8; j++)
            #pragma unroll
            for (int q = 0; q < 4; q++) acc[i][j][q] = 0.f;

    auto issue = [&](int s, int k0) {
        uint32_t stb = sbase + s * STAGE_B;
        #pragma unroll
        for (int t = 0; t < 8; t++) {
            const int tile = t >> 1;
            int w = ((t & 1) << 8) + tid;
            int r = w >> 2, seg = w & 3;
            int sw = seg ^ ((r >> 1) & 3);
            uint32_t dst = stb + tile * TILE_B + r * 64 + sw * 16;
            const __nv_bfloat16* src =
                (tile == 0 ? gA[0] : tile == 1 ? gA[1] : tile == 2 ? gB[0] : gB[1])
                + (size_t)r * K + k0 + seg * 8;
            CP_ASYNC16(dst, src);
        }
    };

    const int frow = lane & 15;
    const int fku  = lane >> 4;

    auto compute = [&](int s) {
        uint32_t stb = sbase + s * STAGE_B;
        #pragma unroll
        for (int ks = 0; ks < 2; ks++) {
            uint32_t ah[2][4], al[2][4];
            #pragma unroll
            for (int mi = 0; mi < 2; mi++) {
                int R = warpM * 32 + mi * 16 + frow;
                int u = (ks * 2 + fku) ^ ((R >> 1) & 3);
                uint32_t ad = stb + (uint32_t)(R * 64 + u * 16);
                ldmx4(ad, ah[mi][0], ah[mi][1], ah[mi][2], ah[mi][3]);
                ldmx4(ad + TILE_B, al[mi][0], al[mi][1], al[mi][2], al[mi][3]);
            }
            #pragma unroll
            for (int np = 0; np < 4; np++) {
                uint32_t bh4[4], bl4[4];
                int R = warpN * 64 + np * 16 + frow;
                int u = (ks * 2 + fku) ^ ((R >> 1) & 3);
                uint32_t bd = stb + 2 * TILE_B + (uint32_t)(R * 64 + u * 16);
                ldmx4(bd, bh4[0], bh4[1], bh4[2], bh4[3]);
                ldmx4(bd + TILE_B, bl4[0], bl4[1], bl4[2], bl4[3]);
                mma16816(acc[0][2*np],   ah[0], bh4[0], bh4[2]);
                mma16816(acc[1][2*np],   ah[1], bh4[0], bh4[2]);
                mma16816(acc[0][2*np+1], ah[0], bh4[1], bh4[3]);
                mma16816(acc[1][2*np+1], ah[1], bh4[1], bh4[3]);
                mma16816(acc[0][2*np],   ah[0], bl4[0], bl4[2]);
                mma16816(acc[1][2*np],   ah[1], bl4[0], bl4[2]);
                mma16816(acc[0][2*np+1], ah[0], bl4[1], bl4[3]);
                mma16816(acc[1][2*np+1], ah[1], bl4[1], bl4[3]);
                mma16816(acc[0][2*np],   al[0], bh4[0], bh4[2]);
                mma16816(acc[1][2*np],   al[1], bh4[0], bh4[2]);
                mma16816(acc[0][2*np+1], al[0], bh4[1], bh4[3]);
                mma16816(acc[1][2*np+1], al[1], bh4[1], bh4[3]);
            }
        }
    };

    const int nch = (K >> 1) >> 5;
    issue(0, kbeg);
    CP_COMMIT();
    issue(1, kbeg + 32);
    CP_COMMIT();
    int sc = 0, si = 2;
    for (int c = 0; c < nch; c++) {
        CP_WAIT1();
        __syncthreads();
        if (c + 2 < nch) {
            issue(si, kbeg + ((c + 2) << 5));
            CP_COMMIT();
            if (++si == 3) si = 0;
        }
        compute(sc);
        if (++sc == 3) sc = 0;
    }

    const int tr = lane >> 2;
    const int tc = (lane & 3) * 2;
    const int grow0 = by * 128 + warpM * 32;
    const int gcol0 = bx * 128 + warpN * 64;
    #pragma unroll
    for (int mi = 0; mi < 2; mi++) {
        #pragma unroll
        for (int ni = 0; ni < 8; ni++) {
            int col = gcol0 + ni * 8 + tc;
            #pragma unroll
            for (int half = 0; half < 2; half++) {
                int row = grow0 + mi * 16 + tr + half * 8;
                *(float2*)(Cz + (size_t)row * N + col) =
                    make_float2(acc[mi][ni][half * 2 + 0], acc[mi][ni][half * 2 + 1]);
            }
        }
    }
}

// ---------------- block reduction ----------------
__device__ __forceinline__ float blockReduceSum(float val) {
    __shared__ float sh[32];
    int lane = threadIdx.x & 31, wid = threadIdx.x >> 5;
    #pragma unroll
    for (int o = 16; o > 0; o >>= 1) val += __shfl_down_sync(0xffffffffu, val, o);
    if (lane == 0) sh[wid] = val;
    __syncthreads();
    val = (threadIdx.x < (blockDim.x >> 5)) ? sh[lane] : 0.0f;
    if (wid == 0) {
        #pragma unroll
        for (int o = 16; o > 0; o >>= 1) val += __shfl_down_sync(0xffffffffu, val, o);
        if (lane == 0) sh[0] = val;
    }
    __syncthreads();
    float r = sh[0];
    __syncthreads();
    return r;
}

// ---------------- split-K reduce: x += p0 + p1 + bias (last layer) ----------
__global__ __launch_bounds__(256) void skred_kernel(const float* __restrict__ p,
                                                    const float* __restrict__ bias,
                                                    float* __restrict__ x) {
    size_t i = (size_t)blockIdx.x * 256 + threadIdx.x;
    const float4 a = ((const float4*)p)[i];
    const float4 b2 = ((const float4*)p)[i + (size_t)BSq * Dq / 4];
    const float4 bv = ((const float4*)bias)[i & (Dq / 4 - 1)];
    float4 xv = ((float4*)x)[i];
    xv.x += a.x + b2.x + bv.x;
    xv.y += a.y + b2.y + bv.y;
    xv.z += a.z + b2.z + bv.z;
    xv.w += a.w + b2.w + bv.w;
    ((float4*)x)[i] = xv;
}

// ---- fused split-K reduce + next-layer LN1 split (one block per row) -------
__global__ __launch_bounds__(256) void skred_ln_kernel(const float* __restrict__ p,
                                                       const float* __restrict__ bias,
                                                       float* __restrict__ x,
                                                       const float* __restrict__ g,
                                                       const float* __restrict__ b,
                                                       __nv_bfloat16* __restrict__ ah,
                                                       __nv_bfloat16* __restrict__ al) {
    int row = blockIdx.x;
    int tid = threadIdx.x;
    size_t i = (size_t)row * (Dq / 4) + tid;
    const float4 a  = ((const float4*)p)[i];
    const float4 b2 = ((const float4*)p)[i + (size_t)BSq * Dq / 4];
    const float4 bv = ((const float4*)bias)[tid];
    float4 xv = ((float4*)x)[i];
    xv.x += a.x + b2.x + bv.x;
    xv.y += a.y + b2.y + bv.y;
    xv.z += a.z + b2.z + bv.z;
    xv.w += a.w + b2.w + bv.w;
    ((float4*)x)[i] = xv;

    // LN over the row (values live in registers)
    float s = xv.x + xv.y + xv.z + xv.w;
    float mean = blockReduceSum(s) * (1.0f / Dq);
    float d0 = xv.x - mean, d1 = xv.y - mean, d2 = xv.z - mean, d3 = xv.w - mean;
    float v = d0 * d0 + d1 * d1 + d2 * d2 + d3 * d3;
    float var = blockReduceSum(v) * (1.0f / Dq);
    float inv = rsqrtf(var + 1e-5f);
    const float4 gv = *(const float4*)(g + tid * 4);
    const float4 bbv = *(const float4*)(b + tid * 4);
    float y0 = d0 * inv * gv.x + bbv.x;
    float y1 = d1 * inv * gv.y + bbv.y;
    float y2 = d2 * inv * gv.z + bbv.z;
    float y3 = d3 * inv * gv.w + bbv.w;
    __nv_bfloat16 h0 = __float2bfloat16(y0);
    __nv_bfloat16 h1 = __float2bfloat16(y1);
    __nv_bfloat16 h2 = __float2bfloat16(y2);
    __nv_bfloat16 h3 = __float2bfloat16(y3);
    size_t off = (size_t)row * Dq + tid * 4;
    *(__nv_bfloat162*)(ah + off)     = __nv_bfloat162(h0, h1);
    *(__nv_bfloat162*)(ah + off + 2) = __nv_bfloat162(h2, h3);
    *(__nv_bfloat162*)(al + off)     = __nv_bfloat162(
        __float2bfloat16(y0 - __bfloat162float(h0)),
        __float2bfloat16(y1 - __bfloat162float(h1)));
    *(__nv_bfloat162*)(al + off + 2) = __nv_bfloat162(
        __float2bfloat16(y2 - __bfloat162float(h2)),
        __float2bfloat16(y3 - __bfloat162float(h3)));
}

// ---------------- flash attention (HMMA, hi/lo, online softmax) -------------
__global__ __launch_bounds__(128) void flash_kernel(const __nv_bfloat16* __restrict__ qh,
                                                    const __nv_bfloat16* __restrict__ ql,
                                                    __nv_bfloat16* __restrict__ oh,
                                                    __nv_bfloat16* __restrict__ ol) {
    __shared__ __nv_bfloat16 sm[4][64][72];
    const int qt = blockIdx.x, z = blockIdx.y;
    const int b = z >> 4, h = z & 15;
    const int tid = threadIdx.x, lane = tid & 31, warp = tid >> 5;
    const int frow = lane & 15, fko = (lane >> 4) << 3;
    const int tr = lane >> 2, tc = lane & 3;

    const size_t qrowbase = (size_t)(b * Sq + qt * 64);

    for (int i = tid; i < 512; i += 128) {
        int r = i >> 3, s = i & 7;
        size_t g = (qrowbase + r) * D3q + h * 64 + s * 8;
        *(uint4*)&sm[0][r][s * 8] = *(const uint4*)(qh + g);
        *(uint4*)&sm[1][r][s * 8] = *(const uint4*)(ql + g);
    }
    __syncthreads();
    uint32_t qfh[4][4], qfl[4][4];
    #pragma unroll
    for (int kc = 0; kc < 4; kc++) {
        ldmx4(smem_u32(&sm[0][warp * 16 + frow][kc * 16 + fko]),
              qfh[kc][0], qfh[kc][1], qfh[kc][2], qfh[kc][3]);
        ldmx4(smem_u32(&sm[1][warp * 16 + frow][kc * 16 + fko]),
              qfl[kc][0], qfl[kc][1], qfl[kc][2], qfl[kc][3]);
    }
    __syncthreads();

    float m0 = -1e30f, m1 = -1e30f, l0 = 0.f, l1 = 0.f;
    float oa[8][4];
    #pragma unroll
    for (int i = 0; i < 8; i++)
        #pragma unroll
        for (int j = 0; j < 4; j++) oa[i][j] = 0.f;

    for (int kt = 0; kt <= qt; kt++) {
        const size_t krowbase = (size_t)(b * Sq + kt * 64);
        for (int i = tid; i < 512; i += 128) {
            int r = i >> 3, s = i & 7;
            size_t gk = (krowbase + r) * D3q + Dq + h * 64 + s * 8;
            size_t gv = (krowbase + r) * D3q + 2 * Dq + h * 64 + s * 8;
            *(uint4*)&sm[0][r][s * 8] = *(const uint4*)(qh + gk);
            *(uint4*)&sm[1][r][s * 8] = *(const uint4*)(ql + gk);
            *(uint4*)&sm[2][r][s * 8] = *(const uint4*)(qh + gv);
            *(uint4*)&sm[3][r][s * 8] = *(const uint4*)(ql + gv);
        }
        __syncthreads();

        float c[8][4];
        #pragma unroll
        for (int i = 0; i < 8; i++)
            #pragma unroll
            for (int j = 0; j < 4; j++) c[i][j] = 0.f;
        #pragma unroll
        for (int kc = 0; kc < 4; kc++) {
            #pragma unroll
            for (int np = 0; np < 4; np++) {
                uint32_t kb[4], kl[4];
                ldmx4(smem_u32(&sm[0][np * 16 + frow][kc * 16 + fko]),
                      kb[0], kb[1], kb[2], kb[3]);
                ldmx4(smem_u32(&sm[1][np * 16 + frow][kc * 16 + fko]),
                      kl[0], kl[1], kl[2], kl[3]);
                mma16816(c[2 * np],     qfh[kc], kb[0], kb[2]);
                mma16816(c[2 * np + 1], qfh[kc], kb[1], kb[3]);
                mma16816(c[2 * np],     qfh[kc], kl[0], kl[2]);
                mma16816(c[2 * np + 1], qfh[kc], kl[1], kl[3]);
                mma16816(c[2 * np],     qfl[kc], kb[0], kb[2]);
                mma16816(c[2 * np + 1], qfl[kc], kb[1], kb[3]);
            }
        }
        #pragma unroll
        for (int nt = 0; nt < 8; nt++)
            #pragma unroll
            for (int e = 0; e < 4; e++) c[nt][e] *= SCALEq;
        if (kt == qt) {
            int row0 = qt * 64 + warp * 16 + tr;
            #pragma unroll
            for (int nt = 0; nt < 8; nt++)
                #pragma unroll
                for (int e = 0; e < 4; e++) {
                    int col = kt * 64 + nt * 8 + tc * 2 + (e & 1);
                    int row = row0 + (e >> 1) * 8;
                    if (col > row) c[nt][e] = -1e30f;
                }
        }
        float r0 = -1e30f, r1 = -1e30f;
        #pragma unroll
        for (int nt = 0; nt < 8; nt++) {
            r0 = fmaxf(r0, fmaxf(c[nt][0], c[nt][1]));
            r1 = fmaxf(r1, fmaxf(c[nt][2], c[nt][3]));
        }
        r0 = fmaxf(r0, __shfl_xor_sync(0xffffffffu, r0, 1));
        r0 = fmaxf(r0, __shfl_xor_sync(0xffffffffu, r0, 2));
        r1 = fmaxf(r1, __shfl_xor_sync(0xffffffffu, r1, 1));
        r1 = fmaxf(r1, __shfl_xor_sync(0xffffffffu, r1, 2));
        float mn0 = fmaxf(m0, r0), mn1 = fmaxf(m1, r1);
        float al0 = __expf(m0 - mn0), al1 = __expf(m1 - mn1);
        float s0 = 0.f, s1 = 0.f;
        #pragma unroll
        for (int nt = 0; nt < 8; nt++) {
            c[nt][0] = __expf(c[nt][0] - mn0); s0 += c[nt][0];
            c[nt][1] = __expf(c[nt][1] - mn0); s0 += c[nt][1];
            c[nt][2] = __expf(c[nt][2] - mn1); s1 += c[nt][2];
            c[nt][3] = __expf(c[nt][3] - mn1); s1 += c[nt][3];
        }
        s0 += __shfl_xor_sync(0xffffffffu, s0, 1);
        s0 += __shfl_xor_sync(0xffffffffu, s0, 2);
        s1 += __shfl_xor_sync(0xffffffffu, s1, 1);
        s1 += __shfl_xor_sync(0xffffffffu, s1, 2);
        l0 = l0 * al0 + s0;
        l1 = l1 * al1 + s1;
        m0 = mn0;
        m1 = mn1;
        #pragma unroll
        for (int nt = 0; nt < 8; nt++) {
            oa[nt][0] *= al0; oa[nt][1] *= al0;
            oa[nt][2] *= al1; oa[nt][3] *= al1;
        }
        #pragma unroll
        for (int kc = 0; kc < 4; kc++) {
            float p[8] = { c[2*kc][0], c[2*kc][1], c[2*kc][2], c[2*kc][3],
                           c[2*kc+1][0], c[2*kc+1][1], c[2*kc+1][2], c[2*kc+1][3] };
            float phf[8], plf[8];
            #pragma unroll
            for (int e = 0; e < 8; e++) {
                phf[e] = __bfloat162float(__float2bfloat16(p[e]));
                plf[e] = p[e] - phf[e];
            }
            uint32_t ph[4] = { pk2(phf[0], phf[1]), pk2(phf[2], phf[3]),
                               pk2(phf[4], phf[5]), pk2(phf[6], phf[7]) };
            uint32_t pl[4] = { pk2(plf[0], plf[1]), pk2(plf[2], plf[3]),
                               pk2(plf[4], plf[5]), pk2(plf[6], plf[7]) };
            #pragma unroll
            for (int np = 0; np < 4; np++) {
                uint32_t vh4[4], vl4[4];
                ldmx4t(smem_u32(&sm[2][kc * 16 + frow][np * 16 + fko]),
                       vh4[0], vh4[1], vh4[2], vh4[3]);
                ldmx4t(smem_u32(&sm[3][kc * 16 + frow][np * 16 + fko]),
                       vl4[0], vl4[1], vl4[2], vl4[3]);
                mma16816(oa[2 * np],     ph, vh4[0], vh4[1]);
                mma16816(oa[2 * np + 1], ph, vh4[2], vh4[3]);
                mma16816(oa[2 * np],     ph, vl4[0], vl4[1]);
                mma16816(oa[2 * np + 1], ph, vl4[2], vl4[3]);
                mma16816(oa[2 * np],     pl, vh4[0], vh4[1]);
                mma16816(oa[2 * np + 1], pl, vh4[2], vh4[3]);
            }
        }
        __syncthreads();
    }

    float inv0 = 1.0f / l0, inv1 = 1.0f / l1;
    #pragma unroll
    for (int nt = 0; nt < 8; nt++) {
        int col = h * 64 + nt * 8 + tc * 2;
        #pragma unroll
        for (int half = 0; half < 2; half++) {
            size_t row = qrowbase + warp * 16 + tr + half * 8;
            float inv = half ? inv1 : inv0;
            float v0 = oa[nt][half * 2 + 0] * inv;
            float v1 = oa[nt][half * 2 + 1] * inv;
            __nv_bfloat16 h0 = __float2bfloat16(v0);
            __nv_bfloat16 h1 = __float2bfloat16(v1);
            size_t off = row * Dq + col;
            *(__nv_bfloat162*)(oh + off) = __nv_bfloat162(h0, h1);
            *(__nv_bfloat162*)(ol + off) = __nv_bfloat162(
                __float2bfloat16(v0 - __bfloat162float(h0)),
                __float2bfloat16(v1 - __bfloat162float(h1)));
        }
    }
}

// ---------------- embedding ----------------
__global__ void embed_kernel(const int* __restrict__ tokens,
                             const float* __restrict__ wte,
                             const float* __restrict__ wpe,
                             float* __restrict__ x) {
    size_t i = (size_t)blockIdx.x * blockDim.x + threadIdx.x;
    int row = (int)(i >> 10);
    int d   = (int)(i & 1023);
    int s   = row & (Sq - 1);
    int tok = tokens[row];
    x[i] = wte[(size_t)tok * Dq + d] + wpe[(size_t)s * Dq + d];
}

// ---------------- layernorm -> bf16 hi/lo (vectorized) ----------------
__global__ __launch_bounds__(256) void ln_split_kernel(const float* __restrict__ x,
                                                       const float* __restrict__ g,
                                                       const float* __restrict__ b,
                                                       __nv_bfloat16* __restrict__ ah,
                                                       __nv_bfloat16* __restrict__ al) {
    int row = blockIdx.x;
    int tid = threadIdx.x;
    const float4 xv = *(const float4*)(x + (size_t)row * Dq + tid * 4);
    float s = xv.x + xv.y + xv.z + xv.w;
    float mean = blockReduceSum(s) * (1.0f / Dq);
    float d0 = xv.x - mean, d1 = xv.y - mean, d2 = xv.z - mean, d3 = xv.w - mean;
    float v = d0 * d0 + d1 * d1 + d2 * d2 + d3 * d3;
    float var = blockReduceSum(v) * (1.0f / Dq);
    float inv = rsqrtf(var + 1e-5f);
    const float4 gv = *(const float4*)(g + tid * 4);
    const float4 bv = *(const float4*)(b + tid * 4);
    float y0 = d0 * inv * gv.x + bv.x;
    float y1 = d1 * inv * gv.y + bv.y;
    float y2 = d2 * inv * gv.z + bv.z;
    float y3 = d3 * inv * gv.w + bv.w;
    __nv_bfloat16 h0 = __float2bfloat16(y0);
    __nv_bfloat16 h1 = __float2bfloat16(y1);
    __nv_bfloat16 h2 = __float2bfloat16(y2);
    __nv_bfloat16 h3 = __float2bfloat16(y3);
    size_t off = (size_t)row * Dq + tid * 4;
    *(__nv_bfloat162*)(ah + off)     = __nv_bfloat162(h0, h1);
    *(__nv_bfloat162*)(ah + off + 2) = __nv_bfloat162(h2, h3);
    *(__nv_bfloat162*)(al + off)     = __nv_bfloat162(
        __float2bfloat16(y0 - __bfloat162float(h0)),
        __float2bfloat16(y1 - __bfloat162float(h1)));
    *(__nv_bfloat162*)(al + off + 2) = __nv_bfloat162(
        __float2bfloat16(y2 - __bfloat162float(h2)),
        __float2bfloat16(y3 - __bfloat162float(h3)));
}

__global__ __launch_bounds__(256) void ln_last_kernel(const float* __restrict__ x,
                                                      const float* __restrict__ g,
                                                      const float* __restrict__ b,
                                                      float* __restrict__ out) {
    int bi = blockIdx.x;
    int row = bi * Sq + (Sq - 1);
    const float* xr = x + (size_t)row * Dq;
    float s = 0.f;
    for (int i = threadIdx.x; i < Dq; i += 256) s += xr[i];
    float mean = blockReduceSum(s) * (1.0f / Dq);
    float v = 0.f;
    for (int i = threadIdx.x; i < Dq; i += 256) { float d0 = xr[i] - mean; v += d0 * d0; }
    float var = blockReduceSum(v) * (1.0f / Dq);
    float inv = rsqrtf(var + 1e-5f);
    float* orow = out + (size_t)bi * Dq;
    for (int i = threadIdx.x; i < Dq; i += 256)
        orow[i] = (xr[i] - mean) * inv * g[i] + b[i];
}

// ---------------- head ----------------
__global__ __launch_bounds__(256) void head_kernel(const float* __restrict__ xf,
                                                   const float* __restrict__ w_head,
                                                   float* __restrict__ out) {
    __shared__ float xs[Bq][Dq];
    for (int i = threadIdx.x; i < Bq * Dq; i += 256)
        xs[i >> 10][i & 1023] = xf[i];
    __syncthreads();
    int v = blockIdx.x * 256 + threadIdx.x;
    if (v >= Vq) return;
    float a0 = 0.f, a1 = 0.f, a2 = 0.f, a3 = 0.f;
    #pragma unroll 4
    for (int d = 0; d < Dq; d++) {
        float w = w_head[(size_t)d * Vq + v];
        a0 += xs[0][d] * w;
        a1 += xs[1][d] * w;
        a2 += xs[2][d] * w;
        a3 += xs[3][d] * w;
    }
    out[v]                  = a0;
    out[(size_t)Vq + v]     = a1;
    out[2 * (size_t)Vq + v] = a2;
    out[3 * (size_t)Vq + v] = a3;
}

// ---------------- launch ----------------
extern "C" void kernel_launch(void* const* d_in, const int* in_sizes, int n_in,
                              void* d_out, int out_size) {
    const int*   tokens = (const int*)  d_in[0];
    const float* wte    = (const float*)d_in[1];
    const float* wpe    = (const float*)d_in[2];
    const float* ln1_g  = (const float*)d_in[3];
    const float* ln1_b  = (const float*)d_in[4];
    const float* wqkv   = (const float*)d_in[5];
    const float* bqkv   = (const float*)d_in[6];
    const float* wo     = (const float*)d_in[7];
    const float* bo     = (const float*)d_in[8];
    const float* ln2_g  = (const float*)d_in[9];
    const float* ln2_b  = (const float*)d_in[10];
    const float* w1     = (const float*)d_in[11];
    const float* b1     = (const float*)d_in[12];
    const float* w2     = (const float*)d_in[13];
    const float* b2     = (const float*)d_in[14];
    const float* lnf_g  = (const float*)d_in[15];
    const float* lnf_b  = (const float*)d_in[16];
    const float* w_head = (const float*)d_in[17];

    float *x, *xf, *pt;
    __nv_bfloat16 *ah, *al, *qh, *ql, *ohp, *olp, *mh, *ml, *bh, *bl;
    cudaGetSymbolAddress((void**)&x,   g_x);
    cudaGetSymbolAddress((void**)&xf,  g_xf);
    cudaGetSymbolAddress((void**)&pt,  g_pt);
    cudaGetSymbolAddress((void**)&ah,  g_ah);
    cudaGetSymbolAddress((void**)&al,  g_al);
    cudaGetSymbolAddress((void**)&qh,  g_qh);
    cudaGetSymbolAddress((void**)&ql,  g_ql);
    cudaGetSymbolAddress((void**)&ohp, g_oh);
    cudaGetSymbolAddress((void**)&olp, g_ol);
    cudaGetSymbolAddress((void**)&mh,  g_mh);
    cudaGetSymbolAddress((void**)&ml,  g_ml);
    cudaGetSymbolAddress((void**)&bh,  g_bh);
    cudaGetSymbolAddress((void**)&bl,  g_bl);

    cudaFuncSetAttribute(hmma_gemm<0,1>, cudaFuncAttributeMaxDynamicSharedMemorySize, HM_SMEM);
    cudaFuncSetAttribute(hmma_gemm<1,0>, cudaFuncAttributeMaxDynamicSharedMemorySize, HM_SMEM);
    cudaFuncSetAttribute(hmma_gemm<2,1>, cudaFuncAttributeMaxDynamicSharedMemorySize, HM_SMEM);
    cudaFuncSetAttribute(hmma_part,      cudaFuncAttributeMaxDynamicSharedMemorySize, HM_SMEM);

    embed_kernel<<<(BSq * Dq) / 256, 256>>>(tokens, wte, wpe, x);
    // layer 0 ln1 (subsequent layers' ln1 are fused into skred_ln)
    ln_split_kernel<<<BSq, 256>>>(x, ln1_g, ln1_b, ah, al);

    for (int l = 0; l < Lq; l++) {
        const float* Wqkv = wqkv + (size_t)l * Dq * D3q;
        const float* Bqkv = bqkv + (size_t)l * D3q;
        const float* Wo   = wo   + (size_t)l * Dq * Dq;
        const float* Bo   = bo   + (size_t)l * Dq;
        const float* W1   = w1   + (size_t)l * Dq * D4q;
        const float* B1   = b1   + (size_t)l * D4q;
        const float* W2   = w2   + (size_t)l * D4q * Dq;
        const float* B2   = b2   + (size_t)l * Dq;

        // ---- attention (ah/al already hold LN1 output) ----
        splitT_kernel<<<dim3(D3q / 32, Dq / 32), 256>>>(Wqkv, bh, bl, Dq, D3q);
        hmma_gemm<0,1><<<dim3(D3q / 128, BSq / 128), 256, HM_SMEM>>>(
            ah, al, bh, bl, Bqkv, nullptr, nullptr, qh, ql, BSq, D3q, Dq);

        flash_kernel<<<dim3(Sq / 64, Bq * Hq), 128>>>(qh, ql, ohp, olp);

        splitT_kernel<<<dim3(Dq / 32, Dq / 32), 256>>>(Wo, bh, bl, Dq, Dq);
        hmma_gemm<1,0><<<dim3(Dq / 128, BSq / 128), 256, HM_SMEM>>>(
            ohp, olp, bh, bl, Bo, x, x, nullptr, nullptr, BSq, Dq, Dq);

        // ---- MLP ----
        ln_split_kernel<<<BSq, 256>>>(x, ln2_g + l * Dq, ln2_b + l * Dq, ah, al);
        splitT_kernel<<<dim3(D4q / 32, Dq / 32), 256>>>(W1, bh, bl, Dq, D4q);
        hmma_gemm<2,1><<<dim3(D4q / 128, BSq / 128), 256, HM_SMEM>>>(
            ah, al, bh, bl, B1, nullptr, nullptr, mh, ml, BSq, D4q, Dq);

        // FC2 with split-K=2; reduce fused with next layer's LN1 (except last)
        splitT_kernel<<<dim3(Dq / 32, D4q / 32), 256>>>(W2, bh, bl, D4q, Dq);
        hmma_part<<<dim3(Dq / 128, BSq / 128, 2), 256, HM_SMEM>>>(
            mh, ml, bh, bl, pt, BSq, Dq, D4q);
        if (l + 1 < Lq) {
            skred_ln_kernel<<<BSq, 256>>>(pt, B2, x,
                                          ln1_g + (l + 1) * Dq, ln1_b + (l + 1) * Dq,
                                          ah, al);
        } else {
            skred_kernel<<<(BSq * Dq / 4) / 256, 256>>>(pt, B2, x);
        }
    }

    ln_last_kernel<<<Bq, 256>>>(x, lnf_g, lnf_b, xf);
    head_kernel<<<(Vq + 255) / 256, 256>>>(xf, w_head, (float*)d_out);
}

// round 17
// speedup vs baseline: 1.0148x; 1.0046x over previous
#include <cuda_runtime.h>
#include <cuda_bf16.h>
#include <math.h>
#include <stdint.h>

// ---------------- problem constants ----------------
#define Bq   4
#define Sq   1024
#define Dq   1024
#define Hq   16
#define Lq   8
#define Vq   50257
#define HDq  64
#define D3q  (3*Dq)
#define D4q  (4*Dq)
#define BSq  (Bq*Sq)
#define SCALEq 0.125f

// ---------------- scratch (device globals) ----------------
__device__ float g_x [(size_t)BSq*Dq];
__device__ float g_xf[Bq*Dq];
__device__ float g_pt[(size_t)2*BSq*Dq];          // split-K fp32 partials (proj/FC2)
__device__ __nv_bfloat16 g_ah[(size_t)BSq*Dq];
__device__ __nv_bfloat16 g_al[(size_t)BSq*Dq];
__device__ __nv_bfloat16 g_qh[(size_t)BSq*D3q];
__device__ __nv_bfloat16 g_ql[(size_t)BSq*D3q];
__device__ __nv_bfloat16 g_oh[(size_t)BSq*Dq];
__device__ __nv_bfloat16 g_ol[(size_t)BSq*Dq];
__device__ __nv_bfloat16 g_mh[(size_t)BSq*D4q];
__device__ __nv_bfloat16 g_ml[(size_t)BSq*D4q];
__device__ __nv_bfloat16 g_bh[(size_t)D4q*Dq];
__device__ __nv_bfloat16 g_bl[(size_t)D4q*Dq];

// ---------------- PTX helpers (sm_80-level, valid on compute_103) ----------
__device__ __forceinline__ uint32_t smem_u32(const void* p) {
    uint32_t a;
    asm("{ .reg .u64 t; cvta.to.shared.u64 t, %1; cvt.u32.u64 %0, t; }" : "=r"(a) : "l"(p));
    return a;
}
#define CP_ASYNC16(dst, src) \
    asm volatile("cp.async.cg.shared.global [%0], [%1], 16;" :: "r"(dst), "l"(src))
#define CP_COMMIT()  asm volatile("cp.async.commit_group;" ::: "memory")
#define CP_WAIT1()   asm volatile("cp.async.wait_group 1;" ::: "memory")
#define CP_WAIT0()   asm volatile("cp.async.wait_group 0;" ::: "memory")

__device__ __forceinline__ void ldmx4(uint32_t addr, uint32_t& r0, uint32_t& r1,
                                      uint32_t& r2, uint32_t& r3) {
    asm volatile("ldmatrix.sync.aligned.m8n8.x4.shared.b16 {%0,%1,%2,%3}, [%4];"
        : "=r"(r0), "=r"(r1), "=r"(r2), "=r"(r3) : "r"(addr));
}
__device__ __forceinline__ void ldmx4t(uint32_t addr, uint32_t& r0, uint32_t& r1,
                                       uint32_t& r2, uint32_t& r3) {
    asm volatile("ldmatrix.sync.aligned.m8n8.x4.trans.shared.b16 {%0,%1,%2,%3}, [%4];"
        : "=r"(r0), "=r"(r1), "=r"(r2), "=r"(r3) : "r"(addr));
}
__device__ __forceinline__ void mma16816(float* c, const uint32_t* a,
                                         uint32_t b0, uint32_t b1) {
    asm volatile("mma.sync.aligned.m16n8k16.row.col.f32.bf16.bf16.f32 "
        "{%0,%1,%2,%3}, {%4,%5,%6,%7}, {%8,%9}, {%0,%1,%2,%3};"
        : "+f"(c[0]), "+f"(c[1]), "+f"(c[2]), "+f"(c[3])
        : "r"(a[0]), "r"(a[1]), "r"(a[2]), "r"(a[3]), "r"(b0), "r"(b1));
}
__device__ __forceinline__ uint32_t pk2(float lo, float hi) {
    uint32_t r;
    asm("cvt.rn.bf16x2.f32 %0, %1, %2;" : "=r"(r) : "f"(hi), "f"(lo));
    return r;
}

// ---------------- transpose + split (vectorized): W [K,N] -> [N,K] hi/lo ----
__global__ __launch_bounds__(256) void splitT_kernel(const float* __restrict__ W,
                                                     __nv_bfloat16* __restrict__ BhT,
                                                     __nv_bfloat16* __restrict__ BlT,
                                                     int K, int N) {
    __shared__ float t[32][33];
    int n0 = blockIdx.x * 32, k0 = blockIdx.y * 32;
    int tid = threadIdx.x;
    {
        int r  = tid >> 3;
        int c4 = tid & 7;
        float4 v = *(const float4*)(W + (size_t)(k0 + r) * N + n0 + c4 * 4);
        t[r][c4 * 4 + 0] = v.x;
        t[r][c4 * 4 + 1] = v.y;
        t[r][c4 * 4 + 2] = v.z;
        t[r][c4 * 4 + 3] = v.w;
    }
    __syncthreads();
    {
        int n = tid >> 3;
        #pragma unroll
        for (int i = 0; i < 2; i++) {
            int kp = (tid & 7) + i * 8;
            int k  = kp * 2;
            float v0 = t[k][n];
            float v1 = t[k + 1][n];
            __nv_bfloat16 h0 = __float2bfloat16(v0);
            __nv_bfloat16 h1 = __float2bfloat16(v1);
            float l0 = v0 - __bfloat162float(h0);
            float l1 = v1 - __bfloat162float(h1);
            size_t off = (size_t)(n0 + n) * K + k0 + k;
            *(__nv_bfloat162*)(BhT + off) = __nv_bfloat162(h0, h1);
            *(__nv_bfloat162*)(BlT + off) =
                __nv_bfloat162(__float2bfloat16(l0), __float2bfloat16(l1));
        }
    }
}

// ---------------- HMMA GEMM (R8/R11-exact body) ------------------------------
#define TILE_B  8192
#define STAGE_B (4*TILE_B)
#define HM_SMEM (3*STAGE_B)

template<int EPI, int OSPLIT>
__global__ __launch_bounds__(256, 2) void hmma_gemm(const __nv_bfloat16* __restrict__ Ah,
                                                    const __nv_bfloat16* __restrict__ Al,
                                                    const __nv_bfloat16* __restrict__ Bh,
                                                    const __nv_bfloat16* __restrict__ Bl,
                                                    const float* __restrict__ bias,
                                                    const float* __restrict__ res,
                                                    float* __restrict__ C,
                                                    __nv_bfloat16* __restrict__ Ch,
                                                    __nv_bfloat16* __restrict__ Cl,
                                                    int M, int N, int K) {
    extern __shared__ char smem[];
    const uint32_t sbase = smem_u32(smem);
    const int tid = threadIdx.x;
    const int lane = tid & 31;
    const int warp = tid >> 5;
    const int warpM = warp & 3;
    const int warpN = warp >> 2;
    const int bx = blockIdx.x, by = blockIdx.y;

    const __nv_bfloat16* gA[2] = { Ah + (size_t)(by * 128) * K,
                                   Al + (size_t)(by * 128) * K };
    const __nv_bfloat16* gB[2] = { Bh + (size_t)(bx * 128) * K,
                                   Bl + (size_t)(bx * 128) * K };

    float acc[2][8][4];
    #pragma unroll
    for (int i = 0; i < 2; i++)
        #pragma unroll
        for (int j = 0; j < 8; j++)
            #pragma unroll
            for (int q = 0; q < 4; q++) acc[i][j][q] = 0.f;

    auto issue = [&](int s, int k0) {
        uint32_t stb = sbase + s * STAGE_B;
        #pragma unroll
        for (int t = 0; t < 8; t++) {
            const int tile = t >> 1;
            int w = ((t & 1) << 8) + tid;
            int r = w >> 2, seg = w & 3;
            int sw = seg ^ ((r >> 1) & 3);
            uint32_t dst = stb + tile * TILE_B + r * 64 + sw * 16;
            const __nv_bfloat16* src =
                (tile == 0 ? gA[0] : tile == 1 ? gA[1] : tile == 2 ? gB[0] : gB[1])
                + (size_t)r * K + k0 + seg * 8;
            CP_ASYNC16(dst, src);
        }
    };

    const int frow = lane & 15;
    const int fku  = lane >> 4;

    auto compute = [&](int s) {
        uint32_t stb = sbase + s * STAGE_B;
        #pragma unroll
        for (int ks = 0; ks < 2; ks++) {
            uint32_t ah[2][4], al[2][4];
            #pragma unroll
            for (int mi = 0; mi < 2; mi++) {
                int R = warpM * 32 + mi * 16 + frow;
                int u = (ks * 2 + fku) ^ ((R >> 1) & 3);
                uint32_t ad = stb + (uint32_t)(R * 64 + u * 16);
                ldmx4(ad, ah[mi][0], ah[mi][1], ah[mi][2], ah[mi][3]);
                ldmx4(ad + TILE_B, al[mi][0], al[mi][1], al[mi][2], al[mi][3]);
            }
            #pragma unroll
            for (int np = 0; np < 4; np++) {
                uint32_t bh4[4], bl4[4];
                int R = warpN * 64 + np * 16 + frow;
                int u = (ks * 2 + fku) ^ ((R >> 1) & 3);
                uint32_t bd = stb + 2 * TILE_B + (uint32_t)(R * 64 + u * 16);
                ldmx4(bd, bh4[0], bh4[1], bh4[2], bh4[3]);
                ldmx4(bd + TILE_B, bl4[0], bl4[1], bl4[2], bl4[3]);
                mma16816(acc[0][2*np],   ah[0], bh4[0], bh4[2]);
                mma16816(acc[1][2*np],   ah[1], bh4[0], bh4[2]);
                mma16816(acc[0][2*np+1], ah[0], bh4[1], bh4[3]);
                mma16816(acc[1][2*np+1], ah[1], bh4[1], bh4[3]);
                mma16816(acc[0][2*np],   ah[0], bl4[0], bl4[2]);
                mma16816(acc[1][2*np],   ah[1], bl4[0], bl4[2]);
                mma16816(acc[0][2*np+1], ah[0], bl4[1], bl4[3]);
                mma16816(acc[1][2*np+1], ah[1], bl4[1], bl4[3]);
                mma16816(acc[0][2*np],   al[0], bh4[0], bh4[2]);
                mma16816(acc[1][2*np],   al[1], bh4[0], bh4[2]);
                mma16816(acc[0][2*np+1], al[0], bh4[1], bh4[3]);
                mma16816(acc[1][2*np+1], al[1], bh4[1], bh4[3]);
            }
        }
    };

    const int nch = K >> 5;
    issue(0, 0);
    CP_COMMIT();
    issue(1, 32);
    CP_COMMIT();
    int sc = 0, si = 2;
    for (int c = 0; c < nch; c++) {
        CP_WAIT1();
        __syncthreads();
        if (c + 2 < nch) {
            issue(si, (c + 2) << 5);
            CP_COMMIT();
            if (++si == 3) si = 0;
        }
        compute(sc);
        if (++sc == 3) sc = 0;
    }

    const int tr = lane >> 2;
    const int tc = (lane & 3) * 2;
    const int grow0 = by * 128 + warpM * 32;
    const int gcol0 = bx * 128 + warpN * 64;
    #pragma unroll
    for (int mi = 0; mi < 2; mi++) {
        #pragma unroll
        for (int ni = 0; ni < 8; ni++) {
            int col = gcol0 + ni * 8 + tc;
            float b0 = bias[col], b1 = bias[col + 1];
            #pragma unroll
            for (int half = 0; half < 2; half++) {
                int row = grow0 + mi * 16 + tr + half * 8;
                float v0 = acc[mi][ni][half * 2 + 0] + b0;
                float v1 = acc[mi][ni][half * 2 + 1] + b1;
                if (EPI == 1) {
                    const float* rp = res + (size_t)row * N + col;
                    v0 += rp[0];
                    v1 += rp[1];
                }
                if (EPI == 2) {
                    v0 = 0.5f * v0 * (1.0f + erff(v0 * 0.70710678118654752f));
                    v1 = 0.5f * v1 * (1.0f + erff(v1 * 0.70710678118654752f));
                }
                if (OSPLIT) {
                    __nv_bfloat16 h0 = __float2bfloat16(v0);
                    __nv_bfloat16 h1 = __float2bfloat16(v1);
                    float l0 = v0 - __bfloat162float(h0);
                    float l1 = v1 - __bfloat162float(h1);
                    size_t off = (size_t)row * N + col;
                    *(__nv_bfloat162*)(Ch + off) = __nv_bfloat162(h0, h1);
                    *(__nv_bfloat162*)(Cl + off) =
                        __nv_bfloat162(__float2bfloat16(l0), __float2bfloat16(l1));
                } else {
                    *(float2*)(C + (size_t)row * N + col) = make_float2(v0, v1);
                }
            }
        }
    }
}

// ---------------- split-K partial GEMM: Cp[z] = A @ B^T over K/2 ------------
__global__ __launch_bounds__(256, 2) void hmma_part(const __nv_bfloat16* __restrict__ Ah,
                                                    const __nv_bfloat16* __restrict__ Al,
                                                    const __nv_bfloat16* __restrict__ Bh,
                                                    const __nv_bfloat16* __restrict__ Bl,
                                                    float* __restrict__ Cp,
                                                    int M, int N, int K) {
    extern __shared__ char smem[];
    const uint32_t sbase = smem_u32(smem);
    const int tid = threadIdx.x;
    const int lane = tid & 31;
    const int warp = tid >> 5;
    const int warpM = warp & 3;
    const int warpN = warp >> 2;
    const int bx = blockIdx.x, by = blockIdx.y;
    const int kbeg = blockIdx.z * (K >> 1);
    float* Cz = Cp + (size_t)blockIdx.z * M * N;

    const __nv_bfloat16* gA[2] = { Ah + (size_t)(by * 128) * K,
                                   Al + (size_t)(by * 128) * K };
    const __nv_bfloat16* gB[2] = { Bh + (size_t)(bx * 128) * K,
                                   Bl + (size_t)(bx * 128) * K };

    float acc[2][8][4];
    #pragma unroll
    for (int i = 0; i < 2; i++)
        #pragma unroll
        for (int j = 0; j < 8; j++)
            #pragma unroll
            for (int q = 0; q < 4; q++) acc[i][j][q] = 0.f;

    auto issue = [&](int s, int k0) {
        uint32_t stb = sbase + s * STAGE_B;
        #pragma unroll
        for (int t = 0; t < 8; t++) {
            const int tile = t >> 1;
            int w = ((t & 1) << 8) + tid;
            int r = w >> 2, seg = w & 3;
            int sw = seg ^ ((r >> 1) & 3);
            uint32_t dst = stb + tile * TILE_B + r * 64 + sw * 16;
            const __nv_bfloat16* src =
                (tile == 0 ? gA[0] : tile == 1 ? gA[1] : tile == 2 ? gB[0] : gB[1])
                + (size_t)r * K + k0 + seg * 8;
            CP_ASYNC16(dst, src);
        }
    };

    const int frow = lane & 15;
    const int fku  = lane >> 4;

    auto compute = [&](int s) {
        uint32_t stb = sbase + s * STAGE_B;
        #pragma unroll
        for (int ks = 0; ks < 2; ks++) {
            uint32_t ah[2][4], al[2][4];
            #pragma unroll
            for (int mi = 0; mi < 2; mi++) {
                int R = warpM * 32 + mi * 16 + frow;
                int u = (ks * 2 + fku) ^ ((R >> 1) & 3);
                uint32_t ad = stb + (uint32_t)(R * 64 + u * 16);
                ldmx4(ad, ah[mi][0], ah[mi][1], ah[mi][2], ah[mi][3]);
                ldmx4(ad + TILE_B, al[mi][0], al[mi][1], al[mi][2], al[mi][3]);
            }
            #pragma unroll
            for (int np = 0; np < 4; np++) {
                uint32_t bh4[4], bl4[4];
                int R = warpN * 64 + np * 16 + frow;
                int u = (ks * 2 + fku) ^ ((R >> 1) & 3);
                uint32_t bd = stb + 2 * TILE_B + (uint32_t)(R * 64 + u * 16);
                ldmx4(bd, bh4[0], bh4[1], bh4[2], bh4[3]);
                ldmx4(bd + TILE_B, bl4[0], bl4[1], bl4[2], bl4[3]);
                mma16816(acc[0][2*np],   ah[0], bh4[0], bh4[2]);
                mma16816(acc[1][2*np],   ah[1], bh4[0], bh4[2]);
                mma16816(acc[0][2*np+1], ah[0], bh4[1], bh4[3]);
                mma16816(acc[1][2*np+1], ah[1], bh4[1], bh4[3]);
                mma16816(acc[0][2*np],   ah[0], bl4[0], bl4[2]);
                mma16816(acc[1][2*np],   ah[1], bl4[0], bl4[2]);
                mma16816(acc[0][2*np+1], ah[0], bl4[1], bl4[3]);
                mma16816(acc[1][2*np+1], ah[1], bl4[1], bl4[3]);
                mma16816(acc[0][2*np],   al[0], bh4[0], bh4[2]);
                mma16816(acc[1][2*np],   al[1], bh4[0], bh4[2]);
                mma16816(acc[0][2*np+1], al[0], bh4[1], bh4[3]);
                mma16816(acc[1][2*np+1], al[1], bh4[1], bh4[3]);
            }
        }
    };

    const int nch = (K >> 1) >> 5;
    issue(0, kbeg);
    CP_COMMIT();
    issue(1, kbeg + 32);
    CP_COMMIT();
    int sc = 0, si = 2;
    for (int c = 0; c < nch; c++) {
        CP_WAIT1();
        __syncthreads();
        if (c + 2 < nch) {
            issue(si, kbeg + ((c + 2) << 5));
            CP_COMMIT();
            if (++si == 3) si = 0;
        }
        compute(sc);
        if (++sc == 3) sc = 0;
    }

    const int tr = lane >> 2;
    const int tc = (lane & 3) * 2;
    const int grow0 = by * 128 + warpM * 32;
    const int gcol0 = bx * 128 + warpN * 64;
    #pragma unroll
    for (int mi = 0; mi < 2; mi++) {
        #pragma unroll
        for (int ni = 0; ni < 8; ni++) {
            int col = gcol0 + ni * 8 + tc;
            #pragma unroll
            for (int half = 0; half < 2; half++) {
                int row = grow0 + mi * 16 + tr + half * 8;
                *(float2*)(Cz + (size_t)row * N + col) =
                    make_float2(acc[mi][ni][half * 2 + 0], acc[mi][ni][half * 2 + 1]);
            }
        }
    }
}

// ---------------- block reduction ----------------
__device__ __forceinline__ float blockReduceSum(float val) {
    __shared__ float sh[32];
    int lane = threadIdx.x & 31, wid = threadIdx.x >> 5;
    #pragma unroll
    for (int o = 16; o > 0; o >>= 1) val += __shfl_down_sync(0xffffffffu, val, o);
    if (lane == 0) sh[wid] = val;
    __syncthreads();
    val = (threadIdx.x < (blockDim.x >> 5)) ? sh[lane] : 0.0f;
    if (wid == 0) {
        #pragma unroll
        for (int o = 16; o > 0; o >>= 1) val += __shfl_down_sync(0xffffffffu, val, o);
        if (lane == 0) sh[0] = val;
    }
    __syncthreads();
    float r = sh[0];
    __syncthreads();
    return r;
}

// ---------------- split-K reduce: x += p0 + p1 + bias (last-layer FC2) ------
__global__ __launch_bounds__(256) void skred_kernel(const float* __restrict__ p,
                                                    const float* __restrict__ bias,
                                                    float* __restrict__ x) {
    size_t i = (size_t)blockIdx.x * 256 + threadIdx.x;
    const float4 a = ((const float4*)p)[i];
    const float4 b2 = ((const float4*)p)[i + (size_t)BSq * Dq / 4];
    const float4 bv = ((const float4*)bias)[i & (Dq / 4 - 1)];
    float4 xv = ((float4*)x)[i];
    xv.x += a.x + b2.x + bv.x;
    xv.y += a.y + b2.y + bv.y;
    xv.z += a.z + b2.z + bv.z;
    xv.w += a.w + b2.w + bv.w;
    ((float4*)x)[i] = xv;
}

// ---- fused split-K reduce + LN split (one block per row) -------------------
// x[row] += p0 + p1 + bias; then LayerNorm(x[row]; g,b) -> ah/al hi/lo.
__global__ __launch_bounds__(256) void skred_ln_kernel(const float* __restrict__ p,
                                                       const float* __restrict__ bias,
                                                       float* __restrict__ x,
                                                       const float* __restrict__ g,
                                                       const float* __restrict__ b,
                                                       __nv_bfloat16* __restrict__ ah,
                                                       __nv_bfloat16* __restrict__ al) {
    int row = blockIdx.x;
    int tid = threadIdx.x;
    size_t i = (size_t)row * (Dq / 4) + tid;
    const float4 a  = ((const float4*)p)[i];
    const float4 b2 = ((const float4*)p)[i + (size_t)BSq * Dq / 4];
    const float4 bv = ((const float4*)bias)[tid];
    float4 xv = ((float4*)x)[i];
    xv.x += a.x + b2.x + bv.x;
    xv.y += a.y + b2.y + bv.y;
    xv.z += a.z + b2.z + bv.z;
    xv.w += a.w + b2.w + bv.w;
    ((float4*)x)[i] = xv;

    float s = xv.x + xv.y + xv.z + xv.w;
    float mean = blockReduceSum(s) * (1.0f / Dq);
    float d0 = xv.x - mean, d1 = xv.y - mean, d2 = xv.z - mean, d3 = xv.w - mean;
    float v = d0 * d0 + d1 * d1 + d2 * d2 + d3 * d3;
    float var = blockReduceSum(v) * (1.0f / Dq);
    float inv = rsqrtf(var + 1e-5f);
    const float4 gv = *(const float4*)(g + tid * 4);
    const float4 bbv = *(const float4*)(b + tid * 4);
    float y0 = d0 * inv * gv.x + bbv.x;
    float y1 = d1 * inv * gv.y + bbv.y;
    float y2 = d2 * inv * gv.z + bbv.z;
    float y3 = d3 * inv * gv.w + bbv.w;
    __nv_bfloat16 h0 = __float2bfloat16(y0);
    __nv_bfloat16 h1 = __float2bfloat16(y1);
    __nv_bfloat16 h2 = __float2bfloat16(y2);
    __nv_bfloat16 h3 = __float2bfloat16(y3);
    size_t off = (size_t)row * Dq + tid * 4;
    *(__nv_bfloat162*)(ah + off)     = __nv_bfloat162(h0, h1);
    *(__nv_bfloat162*)(ah + off + 2) = __nv_bfloat162(h2, h3);
    *(__nv_bfloat162*)(al + off)     = __nv_bfloat162(
        __float2bfloat16(y0 - __bfloat162float(h0)),
        __float2bfloat16(y1 - __bfloat162float(h1)));
    *(__nv_bfloat162*)(al + off + 2) = __nv_bfloat162(
        __float2bfloat16(y2 - __bfloat162float(h2)),
        __float2bfloat16(y3 - __bfloat162float(h3)));
}

// ---------------- flash attention (HMMA, hi/lo, online softmax) -------------
__global__ __launch_bounds__(128) void flash_kernel(const __nv_bfloat16* __restrict__ qh,
                                                    const __nv_bfloat16* __restrict__ ql,
                                                    __nv_bfloat16* __restrict__ oh,
                                                    __nv_bfloat16* __restrict__ ol) {
    __shared__ __nv_bfloat16 sm[4][64][72];
    const int qt = blockIdx.x, z = blockIdx.y;
    const int b = z >> 4, h = z & 15;
    const int tid = threadIdx.x, lane = tid & 31, warp = tid >> 5;
    const int frow = lane & 15, fko = (lane >> 4) << 3;
    const int tr = lane >> 2, tc = lane & 3;

    const size_t qrowbase = (size_t)(b * Sq + qt * 64);

    for (int i = tid; i < 512; i += 128) {
        int r = i >> 3, s = i & 7;
        size_t g = (qrowbase + r) * D3q + h * 64 + s * 8;
        *(uint4*)&sm[0][r][s * 8] = *(const uint4*)(qh + g);
        *(uint4*)&sm[1][r][s * 8] = *(const uint4*)(ql + g);
    }
    __syncthreads();
    uint32_t qfh[4][4], qfl[4][4];
    #pragma unroll
    for (int kc = 0; kc < 4; kc++) {
        ldmx4(smem_u32(&sm[0][warp * 16 + frow][kc * 16 + fko]),
              qfh[kc][0], qfh[kc][1], qfh[kc][2], qfh[kc][3]);
        ldmx4(smem_u32(&sm[1][warp * 16 + frow][kc * 16 + fko]),
              qfl[kc][0], qfl[kc][1], qfl[kc][2], qfl[kc][3]);
    }
    __syncthreads();

    float m0 = -1e30f, m1 = -1e30f, l0 = 0.f, l1 = 0.f;
    float oa[8][4];
    #pragma unroll
    for (int i = 0; i < 8; i++)
        #pragma unroll
        for (int j = 0; j < 4; j++) oa[i][j] = 0.f;

    for (int kt = 0; kt <= qt; kt++) {
        const size_t krowbase = (size_t)(b * Sq + kt * 64);
        for (int i = tid; i < 512; i += 128) {
            int r = i >> 3, s = i & 7;
            size_t gk = (krowbase + r) * D3q + Dq + h * 64 + s * 8;
            size_t gv = (krowbase + r) * D3q + 2 * Dq + h * 64 + s * 8;
            *(uint4*)&sm[0][r][s * 8] = *(const uint4*)(qh + gk);
            *(uint4*)&sm[1][r][s * 8] = *(const uint4*)(ql + gk);
            *(uint4*)&sm[2][r][s * 8] = *(const uint4*)(qh + gv);
            *(uint4*)&sm[3][r][s * 8] = *(const uint4*)(ql + gv);
        }
        __syncthreads();

        float c[8][4];
        #pragma unroll
        for (int i = 0; i < 8; i++)
            #pragma unroll
            for (int j = 0; j < 4; j++) c[i][j] = 0.f;
        #pragma unroll
        for (int kc = 0; kc < 4; kc++) {
            #pragma unroll
            for (int np = 0; np < 4; np++) {
                uint32_t kb[4], kl[4];
                ldmx4(smem_u32(&sm[0][np * 16 + frow][kc * 16 + fko]),
                      kb[0], kb[1], kb[2], kb[3]);
                ldmx4(smem_u32(&sm[1][np * 16 + frow][kc * 16 + fko]),
                      kl[0], kl[1], kl[2], kl[3]);
                mma16816(c[2 * np],     qfh[kc], kb[0], kb[2]);
                mma16816(c[2 * np + 1], qfh[kc], kb[1], kb[3]);
                mma16816(c[2 * np],     qfh[kc], kl[0], kl[2]);
                mma16816(c[2 * np + 1], qfh[kc], kl[1], kl[3]);
                mma16816(c[2 * np],     qfl[kc], kb[0], kb[2]);
                mma16816(c[2 * np + 1], qfl[kc], kb[1], kb[3]);
            }
        }
        #pragma unroll
        for (int nt = 0; nt < 8; nt++)
            #pragma unroll
            for (int e = 0; e < 4; e++) c[nt][e] *= SCALEq;
        if (kt == qt) {
            int row0 = qt * 64 + warp * 16 + tr;
            #pragma unroll
            for (int nt = 0; nt < 8; nt++)
                #pragma unroll
                for (int e = 0; e < 4; e++) {
                    int col = kt * 64 + nt * 8 + tc * 2 + (e & 1);
                    int row = row0 + (e >> 1) * 8;
                    if (col > row) c[nt][e] = -1e30f;
                }
        }
        float r0 = -1e30f, r1 = -1e30f;
        #pragma unroll
        for (int nt = 0; nt < 8; nt++) {
            r0 = fmaxf(r0, fmaxf(c[nt][0], c[nt][1]));
            r1 = fmaxf(r1, fmaxf(c[nt][2], c[nt][3]));
        }
        r0 = fmaxf(r0, __shfl_xor_sync(0xffffffffu, r0, 1));
        r0 = fmaxf(r0, __shfl_xor_sync(0xffffffffu, r0, 2));
        r1 = fmaxf(r1, __shfl_xor_sync(0xffffffffu, r1, 1));
        r1 = fmaxf(r1, __shfl_xor_sync(0xffffffffu, r1, 2));
        float mn0 = fmaxf(m0, r0), mn1 = fmaxf(m1, r1);
        float al0 = __expf(m0 - mn0), al1 = __expf(m1 - mn1);
        float s0 = 0.f, s1 = 0.f;
        #pragma unroll
        for (int nt = 0; nt < 8; nt++) {
            c[nt][0] = __expf(c[nt][0] - mn0); s0 += c[nt][0];
            c[nt][1] = __expf(c[nt][1] - mn0); s0 += c[nt][1];
            c[nt][2] = __expf(c[nt][2] - mn1); s1 += c[nt][2];
            c[nt][3] = __expf(c[nt][3] - mn1); s1 += c[nt][3];
        }
        s0 += __shfl_xor_sync(0xffffffffu, s0, 1);
        s0 += __shfl_xor_sync(0xffffffffu, s0, 2);
        s1 += __shfl_xor_sync(0xffffffffu, s1, 1);
        s1 += __shfl_xor_sync(0xffffffffu, s1, 2);
        l0 = l0 * al0 + s0;
        l1 = l1 * al1 + s1;
        m0 = mn0;
        m1 = mn1;
        #pragma unroll
        for (int nt = 0; nt < 8; nt++) {
            oa[nt][0] *= al0; oa[nt][1] *= al0;
            oa[nt][2] *= al1; oa[nt][3] *= al1;
        }
        #pragma unroll
        for (int kc = 0; kc < 4; kc++) {
            float p[8] = { c[2*kc][0], c[2*kc][1], c[2*kc][2], c[2*kc][3],
                           c[2*kc+1][0], c[2*kc+1][1], c[2*kc+1][2], c[2*kc+1][3] };
            float phf[8], plf[8];
            #pragma unroll
            for (int e = 0; e < 8; e++) {
                phf[e] = __bfloat162float(__float2bfloat16(p[e]));
                plf[e] = p[e] - phf[e];
            }
            uint32_t ph[4] = { pk2(phf[0], phf[1]), pk2(phf[2], phf[3]),
                               pk2(phf[4], phf[5]), pk2(phf[6], phf[7]) };
            uint32_t pl[4] = { pk2(plf[0], plf[1]), pk2(plf[2], plf[3]),
                               pk2(plf[4], plf[5]), pk2(plf[6], plf[7]) };
            #pragma unroll
            for (int np = 0; np < 4; np++) {
                uint32_t vh4[4], vl4[4];
                ldmx4t(smem_u32(&sm[2][kc * 16 + frow][np * 16 + fko]),
                       vh4[0], vh4[1], vh4[2], vh4[3]);
                ldmx4t(smem_u32(&sm[3][kc * 16 + frow][np * 16 + fko]),
                       vl4[0], vl4[1], vl4[2], vl4[3]);
                mma16816(oa[2 * np],     ph, vh4[0], vh4[1]);
                mma16816(oa[2 * np + 1], ph, vh4[2], vh4[3]);
                mma16816(oa[2 * np],     ph, vl4[0], vl4[1]);
                mma16816(oa[2 * np + 1], ph, vl4[2], vl4[3]);
                mma16816(oa[2 * np],     pl, vh4[0], vh4[1]);
                mma16816(oa[2 * np + 1], pl, vh4[2], vh4[3]);
            }
        }
        __syncthreads();
    }

    float inv0 = 1.0f / l0, inv1 = 1.0f / l1;
    #pragma unroll
    for (int nt = 0; nt < 8; nt++) {
        int col = h * 64 + nt * 8 + tc * 2;
        #pragma unroll
        for (int half = 0; half < 2; half++) {
            size_t row = qrowbase + warp * 16 + tr + half * 8;
            float inv = half ? inv1 : inv0;
            float v0 = oa[nt][half * 2 + 0] * inv;
            float v1 = oa[nt][half * 2 + 1] * inv;
            __nv_bfloat16 h0 = __float2bfloat16(v0);
            __nv_bfloat16 h1 = __float2bfloat16(v1);
            size_t off = row * Dq + col;
            *(__nv_bfloat162*)(oh + off) = __nv_bfloat162(h0, h1);
            *(__nv_bfloat162*)(ol + off) = __nv_bfloat162(
                __float2bfloat16(v0 - __bfloat162float(h0)),
                __float2bfloat16(v1 - __bfloat162float(h1)));
        }
    }
}

// ---------------- embedding ----------------
__global__ void embed_kernel(const int* __restrict__ tokens,
                             const float* __restrict__ wte,
                             const float* __restrict__ wpe,
                             float* __restrict__ x) {
    size_t i = (size_t)blockIdx.x * blockDim.x + threadIdx.x;
    int row = (int)(i >> 10);
    int d   = (int)(i & 1023);
    int s   = row & (Sq - 1);
    int tok = tokens[row];
    x[i] = wte[(size_t)tok * Dq + d] + wpe[(size_t)s * Dq + d];
}

// ---------------- layernorm -> bf16 hi/lo (vectorized; layer-0 LN1) ---------
__global__ __launch_bounds__(256) void ln_split_kernel(const float* __restrict__ x,
                                                       const float* __restrict__ g,
                                                       const float* __restrict__ b,
                                                       __nv_bfloat16* __restrict__ ah,
                                                       __nv_bfloat16* __restrict__ al) {
    int row = blockIdx.x;
    int tid = threadIdx.x;
    const float4 xv = *(const float4*)(x + (size_t)row * Dq + tid * 4);
    float s = xv.x + xv.y + xv.z + xv.w;
    float mean = blockReduceSum(s) * (1.0f / Dq);
    float d0 = xv.x - mean, d1 = xv.y - mean, d2 = xv.z - mean, d3 = xv.w - mean;
    float v = d0 * d0 + d1 * d1 + d2 * d2 + d3 * d3;
    float var = blockReduceSum(v) * (1.0f / Dq);
    float inv = rsqrtf(var + 1e-5f);
    const float4 gv = *(const float4*)(g + tid * 4);
    const float4 bv = *(const float4*)(b + tid * 4);
    float y0 = d0 * inv * gv.x + bv.x;
    float y1 = d1 * inv * gv.y + bv.y;
    float y2 = d2 * inv * gv.z + bv.z;
    float y3 = d3 * inv * gv.w + bv.w;
    __nv_bfloat16 h0 = __float2bfloat16(y0);
    __nv_bfloat16 h1 = __float2bfloat16(y1);
    __nv_bfloat16 h2 = __float2bfloat16(y2);
    __nv_bfloat16 h3 = __float2bfloat16(y3);
    size_t off = (size_t)row * Dq + tid * 4;
    *(__nv_bfloat162*)(ah + off)     = __nv_bfloat162(h0, h1);
    *(__nv_bfloat162*)(ah + off + 2) = __nv_bfloat162(h2, h3);
    *(__nv_bfloat162*)(al + off)     = __nv_bfloat162(
        __float2bfloat16(y0 - __bfloat162float(h0)),
        __float2bfloat16(y1 - __bfloat162float(h1)));
    *(__nv_bfloat162*)(al + off + 2) = __nv_bfloat162(
        __float2bfloat16(y2 - __bfloat162float(h2)),
        __float2bfloat16(y3 - __bfloat162float(h3)));
}

__global__ __launch_bounds__(256) void ln_last_kernel(const float* __restrict__ x,
                                                      const float* __restrict__ g,
                                                      const float* __restrict__ b,
                                                      float* __restrict__ out) {
    int bi = blockIdx.x;
    int row = bi * Sq + (Sq - 1);
    const float* xr = x + (size_t)row * Dq;
    float s = 0.f;
    for (int i = threadIdx.x; i < Dq; i += 256) s += xr[i];
    float mean = blockReduceSum(s) * (1.0f / Dq);
    float v = 0.f;
    for (int i = threadIdx.x; i < Dq; i += 256) { float d0 = xr[i] - mean; v += d0 * d0; }
    float var = blockReduceSum(v) * (1.0f / Dq);
    float inv = rsqrtf(var + 1e-5f);
    float* orow = out + (size_t)bi * Dq;
    for (int i = threadIdx.x; i < Dq; i += 256)
        orow[i] = (xr[i] - mean) * inv * g[i] + b[i];
}

// ---------------- head ----------------
__global__ __launch_bounds__(256) void head_kernel(const float* __restrict__ xf,
                                                   const float* __restrict__ w_head,
                                                   float* __restrict__ out) {
    __shared__ float xs[Bq][Dq];
    for (int i = threadIdx.x; i < Bq * Dq; i += 256)
        xs[i >> 10][i & 1023] = xf[i];
    __syncthreads();
    int v = blockIdx.x * 256 + threadIdx.x;
    if (v >= Vq) return;
    float a0 = 0.f, a1 = 0.f, a2 = 0.f, a3 = 0.f;
    #pragma unroll 4
    for (int d = 0; d < Dq; d++) {
        float w = w_head[(size_t)d * Vq + v];
        a0 += xs[0][d] * w;
        a1 += xs[1][d] * w;
        a2 += xs[2][d] * w;
        a3 += xs[3][d] * w;
    }
    out[v]                  = a0;
    out[(size_t)Vq + v]     = a1;
    out[2 * (size_t)Vq + v] = a2;
    out[3 * (size_t)Vq + v] = a3;
}

// ---------------- launch ----------------
extern "C" void kernel_launch(void* const* d_in, const int* in_sizes, int n_in,
                              void* d_out, int out_size) {
    const int*   tokens = (const int*)  d_in[0];
    const float* wte    = (const float*)d_in[1];
    const float* wpe    = (const float*)d_in[2];
    const float* ln1_g  = (const float*)d_in[3];
    const float* ln1_b  = (const float*)d_in[4];
    const float* wqkv   = (const float*)d_in[5];
    const float* bqkv   = (const float*)d_in[6];
    const float* wo     = (const float*)d_in[7];
    const float* bo     = (const float*)d_in[8];
    const float* ln2_g  = (const float*)d_in[9];
    const float* ln2_b  = (const float*)d_in[10];
    const float* w1     = (const float*)d_in[11];
    const float* b1     = (const float*)d_in[12];
    const float* w2     = (const float*)d_in[13];
    const float* b2     = (const float*)d_in[14];
    const float* lnf_g  = (const float*)d_in[15];
    const float* lnf_b  = (const float*)d_in[16];
    const float* w_head = (const float*)d_in[17];

    float *x, *xf, *pt;
    __nv_bfloat16 *ah, *al, *qh, *ql, *ohp, *olp, *mh, *ml, *bh, *bl;
    cudaGetSymbolAddress((void**)&x,   g_x);
    cudaGetSymbolAddress((void**)&xf,  g_xf);
    cudaGetSymbolAddress((void**)&pt,  g_pt);
    cudaGetSymbolAddress((void**)&ah,  g_ah);
    cudaGetSymbolAddress((void**)&al,  g_al);
    cudaGetSymbolAddress((void**)&qh,  g_qh);
    cudaGetSymbolAddress((void**)&ql,  g_ql);
    cudaGetSymbolAddress((void**)&ohp, g_oh);
    cudaGetSymbolAddress((void**)&olp, g_ol);
    cudaGetSymbolAddress((void**)&mh,  g_mh);
    cudaGetSymbolAddress((void**)&ml,  g_ml);
    cudaGetSymbolAddress((void**)&bh,  g_bh);
    cudaGetSymbolAddress((void**)&bl,  g_bl);

    cudaFuncSetAttribute(hmma_gemm<0,1>, cudaFuncAttributeMaxDynamicSharedMemorySize, HM_SMEM);
    cudaFuncSetAttribute(hmma_gemm<2,1>, cudaFuncAttributeMaxDynamicSharedMemorySize, HM_SMEM);
    cudaFuncSetAttribute(hmma_part,      cudaFuncAttributeMaxDynamicSharedMemorySize, HM_SMEM);

    embed_kernel<<<(BSq * Dq) / 256, 256>>>(tokens, wte, wpe, x);
    // layer 0 LN1 (later layers' LN1 fused into FC2's skred_ln)
    ln_split_kernel<<<BSq, 256>>>(x, ln1_g, ln1_b, ah, al);

    for (int l = 0; l < Lq; l++) {
        const float* Wqkv = wqkv + (size_t)l * Dq * D3q;
        const float* Bqkv = bqkv + (size_t)l * D3q;
        const float* Wo   = wo   + (size_t)l * Dq * Dq;
        const float* Bo   = bo   + (size_t)l * Dq;
        const float* W1   = w1   + (size_t)l * Dq * D4q;
        const float* B1   = b1   + (size_t)l * D4q;
        const float* W2   = w2   + (size_t)l * D4q * Dq;
        const float* B2   = b2   + (size_t)l * Dq;

        // ---- attention (ah/al already hold LN1 output) ----
        splitT_kernel<<<dim3(D3q / 32, Dq / 32), 256>>>(Wqkv, bh, bl, Dq, D3q);
        hmma_gemm<0,1><<<dim3(D3q / 128, BSq / 128), 256, HM_SMEM>>>(
            ah, al, bh, bl, Bqkv, nullptr, nullptr, qh, ql, BSq, D3q, Dq);

        flash_kernel<<<dim3(Sq / 64, Bq * Hq), 128>>>(qh, ql, ohp, olp);

        // proj with split-K=2; reduce fused with LN2 -> ah/al
        splitT_kernel<<<dim3(Dq / 32, Dq / 32), 256>>>(Wo, bh, bl, Dq, Dq);
        hmma_part<<<dim3(Dq / 128, BSq / 128, 2), 256, HM_SMEM>>>(
            ohp, olp, bh, bl, pt, BSq, Dq, Dq);
        skred_ln_kernel<<<BSq, 256>>>(pt, Bo, x,
                                      ln2_g + (size_t)l * Dq, ln2_b + (size_t)l * Dq,
                                      ah, al);

        // ---- MLP ----
        splitT_kernel<<<dim3(D4q / 32, Dq / 32), 256>>>(W1, bh, bl, Dq, D4q);
        hmma_gemm<2,1><<<dim3(D4q / 128, BSq / 128), 256, HM_SMEM>>>(
            ah, al, bh, bl, B1, nullptr, nullptr, mh, ml, BSq, D4q, Dq);

        // FC2 with split-K=2; reduce fused with next layer's LN1 (except last)
        splitT_kernel<<<dim3(Dq / 32, D4q / 32), 256>>>(W2, bh, bl, D4q, Dq);
        hmma_part<<<dim3(Dq / 128, BSq / 128, 2), 256, HM_SMEM>>>(
            mh, ml, bh, bl, pt, BSq, Dq, D4q);
        if (l + 1 < Lq) {
            skred_ln_kernel<<<BSq, 256>>>(pt, B2, x,
                                          ln1_g + (size_t)(l + 1) * Dq,
                                          ln1_b + (size_t)(l + 1) * Dq,
                                          ah, al);
        } else {
            skred_kernel<<<(BSq * Dq / 4) / 256, 256>>>(pt, B2, x);
        }
    }

    ln_last_kernel<<<Bq, 256>>>(x, lnf_g, lnf_b, xf);
    head_kernel<<<(Vq + 255) / 256, 256>>>(xf, w_head, (float*)d_out);
}